// round 14
// baseline (speedup 1.0000x reference)
#include <cuda_runtime.h>
#include <cuda_fp16.h>
#include <math.h>
#include <stdint.h>

// ---------------------------------------------------------------------------
// B=2, T=24, H=256, W=256, N=512, HIDDEN=256
// conv1: fused, direct-LDS A, dense K=160, 2 output rows/block
// conv2: 3x3x64->128 s2  implicit GEMM mma fp16, 4-stage pipeline
// conv3: 3x3x128->256 s2 implicit GEMM mma fp16, 4-stage pipeline
// corr : [48] 512x1024x256 GEMM mma fp16 -> corr fp16
// ---------------------------------------------------------------------------

__device__ __half g_f1[2 * 24 * 128 * 128 * 64];          // 100 MB
__device__ __half g_f2[2 * 24 * 64 * 64 * 128];           //  50 MB
__device__ __half g_f3[2 * 24 * 32 * 32 * 256];           //  25 MB
__device__ __half g_qh[2 * 512 * 256];
__device__ __half g_corrh[2 * 24 * 512 * 1024];           //  50 MB (fp16 corr)
__device__ __half g_w1h[64 * 160];                        // conv1 W [cout][160]
__device__ __half g_w2h[128 * 576];
__device__ __half g_w3h[256 * 1152];

// ---------------------------------------------------------------------------
// helpers
// ---------------------------------------------------------------------------
__device__ __forceinline__ uint32_t smem_u32(const void* p) {
    uint32_t a;
    asm("{ .reg .u64 t; cvta.to.shared.u64 t, %1; cvt.u32.u64 %0, t; }"
        : "=r"(a) : "l"(p));
    return a;
}

__device__ __forceinline__ void cp16(uint32_t dst, const void* gsrc, uint32_t ss) {
    asm volatile(
        "{ .reg .u64 g; cvta.to.global.u64 g, %1;"
        "  cp.async.ca.shared.global [%0], [g], 16, %2; }"
        :: "r"(dst), "l"(gsrc), "r"(ss) : "memory");
}
#define CP_COMMIT() asm volatile("cp.async.commit_group;" ::: "memory")
#define CP_WAIT2()  asm volatile("cp.async.wait_group 2;" ::: "memory")
#define CP_WAIT1()  asm volatile("cp.async.wait_group 1;" ::: "memory")
#define CP_WAIT0()  asm volatile("cp.async.wait_group 0;" ::: "memory")

__device__ __forceinline__ void ldmx4(uint32_t* r, uint32_t addr) {
    asm volatile(
        "ldmatrix.sync.aligned.m8n8.x4.shared.b16 {%0,%1,%2,%3}, [%4];"
        : "=r"(r[0]), "=r"(r[1]), "=r"(r[2]), "=r"(r[3]) : "r"(addr));
}

__device__ __forceinline__ uint32_t lds32(uint32_t addr) {
    uint32_t v;
    asm volatile("ld.shared.b32 %0, [%1];" : "=r"(v) : "r"(addr));
    return v;
}

__device__ __forceinline__ void mma_f16(float* d, const uint32_t* a,
                                        const uint32_t* b) {
    asm volatile(
        "mma.sync.aligned.m16n8k16.row.col.f32.f16.f16.f32 "
        "{%0,%1,%2,%3}, {%4,%5,%6,%7}, {%8,%9}, {%0,%1,%2,%3};"
        : "+f"(d[0]), "+f"(d[1]), "+f"(d[2]), "+f"(d[3])
        : "r"(a[0]), "r"(a[1]), "r"(a[2]), "r"(a[3]), "r"(b[0]), "r"(b[1]));
}

__device__ __forceinline__ uint32_t packh2(float a, float b) {
    __half2 t = __floats2half2_rn(a, b);
    return *reinterpret_cast<uint32_t*>(&t);
}

// smem tile: rows x 32 fp16, row stride 80 B (16B pad, conflict-free ldmatrix)
#define RS    80
#define MATB  (128 * RS)            // 10240 B (128-row tile)
#define STG2  (2 * MATB)            // A | B (single-pass)
#define DSMEM_CONV (4 * STG2)       // 81920 B, 4-stage pipeline

// conv1 v5 (2 rows/block): B (5 chunks x 64 rows x RS) + V (10 rows: 9 video + 1 zero)
#define C1_B    0
#define C1_V    (5 * 64 * RS)             // 25600
#define C1_VROW 1600
#define DSMEM_C1 (C1_V + 10 * C1_VROW)    // 41600

// ---------------------------------------------------------------------------
// conv1 weight prep: dense-K layout. k = dy*22 + r, r = dx*3+ci (r<21),
// zero at r=21 and k>=154.
// ---------------------------------------------------------------------------
__global__ void __launch_bounds__(256) prep_w1_kernel(const float* __restrict__ w)
{
    int i = blockIdx.x * 256 + threadIdx.x;   // 64*160
    if (i >= 64 * 160) return;
    int c = i / 160, kk = i - c * 160;
    int dy = kk / 22, r = kk - dy * 22;
    float v = (dy < 7 && r < 21) ? w[(dy * 21 + r) * 64 + c] : 0.f;
    g_w1h[i] = __float2half(v);
}

// w[k][cout] -> wt[cout][k] fp16
__global__ void __launch_bounds__(256) transpose_w(
    const float* __restrict__ w, __half* __restrict__ h, int K, int C)
{
    int i = blockIdx.x * 256 + threadIdx.x;
    if (i < K * C) {
        int k = i / C, c = i - k * C;
        h[(size_t)c * K + k] = __float2half(w[i]);
    }
}

// ---------------------------------------------------------------------------
// conv1 fused v5: one block = TWO output rows (bt, yp..yp+1) = 256 px (M).
// Tile rows [0,128) = output row yp, [128,256) = yp+1 (srow = wm>>1).
// A[x][dy*22+r] = vsm[dy + 2*srow][6x + r]; dy==7 (pad) -> zero row 9.
// K = 160 (5 chunks). No A staging, no mainloop syncs.
// ---------------------------------------------------------------------------
__global__ void __launch_bounds__(256, 2) conv1_fused_kernel(
    const float* __restrict__ video,
    const float* __restrict__ bias)
{
    extern __shared__ char sm[];
    __shared__ float s_bias[64];

    int tid  = threadIdx.x;
    int lane = tid & 31;
    int wid  = tid >> 5;
    int wm   = wid & 3;          // 4 M-warps (64 rows each)
    int wn   = wid >> 2;         // 2 N-warps (32 cols each)

    int yp = (blockIdx.x & 63) * 2;
    int bt = blockIdx.x >> 6;

    if (tid < 64) s_bias[tid] = bias[tid];

    uint32_t smb = smem_u32(sm);

    // B preload: 5 chunks x 64 rows x 4 segs = 1280 cp16
    for (int u = tid; u < 1280; u += 256) {
        int seg = u & 3;
        int cc  = (u >> 2) % 5;
        int r   = u / 20;
        const __half* s = g_w1h + r * 160 + cc * 32 + seg * 8;
        uint32_t d = smb + C1_B + (cc * 64 + r) * RS + seg * 16;
        cp16(d, s, 16u);
    }
    CP_COMMIT();

    // zero video smem: 10 rows (9 video + zero row 9)
    uint32_t* vz = reinterpret_cast<uint32_t*>(sm + C1_V);
    for (int u = tid; u < 10 * C1_VROW / 4; u += 256) vz[u] = 0u;
    __syncthreads();

    // video rows j=0..8: iy = 2*yp + j - 2; 768 floats -> halfs slot [6..773]
    const float inv255 = 1.0f / 255.0f;
    for (int u = tid; u < 9 * 384; u += 256) {
        int j = u / 384;
        int m = u - j * 384;
        int iy = 2 * yp + j - 2;
        if ((unsigned)iy < 256u) {
            const float2 v2 = *reinterpret_cast<const float2*>(
                video + ((size_t)(bt * 256 + iy) * 256) * 3 + 2 * m);
            uint32_t pk = packh2(v2.x * inv255, v2.y * inv255);
            *reinterpret_cast<uint32_t*>(sm + C1_V + j * C1_VROW + 12 + 4 * m) = pk;
        }
    }
    CP_WAIT0();
    __syncthreads();

    int srow = wm >> 1;          // which output row this warp's tile rows map to
    uint32_t xb0 = 12u * ((wm & 1) * 64 + (lane >> 2));   // 6x * 2 bytes
    int klane = 2 * (lane & 3);

    int boff = (((lane >> 4) * 8 + (lane & 7)) * RS) + (((lane >> 3) & 1) * 8) * 2;

    float acc[4][4][4];
#pragma unroll
    for (int i = 0; i < 4; i++)
#pragma unroll
        for (int j = 0; j < 4; j++)
#pragma unroll
            for (int k = 0; k < 4; k++) acc[i][j][k] = 0.0f;

    // sync-free mainloop: 5 chunks x 2 ks, 4 M-tiles each
#pragma unroll
    for (int cc = 0; cc < 5; cc++) {
        uint32_t bb = smb + C1_B + cc * (64 * RS);
#pragma unroll
        for (int ks = 0; ks < 2; ks++) {
            uint32_t bh[8];
#pragma unroll
            for (int q = 0; q < 2; q++) {
                uint32_t ro = boff + (wn * 32 + q * 16) * RS + ks * 32;
                ldmx4(&bh[4 * q], bb + ro);
            }
            int k0  = cc * 32 + ks * 16 + klane;
            int dy0 = k0 / 22, r0 = k0 - 22 * dy0;
            int k2  = k0 + 8;
            int dy2 = k2 / 22, r2 = k2 - 22 * dy2;
            int j0 = (dy0 < 7) ? (dy0 + 2 * srow) : 9;
            int j2 = (dy2 < 7) ? (dy2 + 2 * srow) : 9;
            uint32_t a0b = smb + C1_V + j0 * C1_VROW + r0 * 2 + xb0;
            uint32_t a2b = smb + C1_V + j2 * C1_VROW + r2 * 2 + xb0;
#pragma unroll
            for (int mt = 0; mt < 4; mt++) {
                uint32_t af[4];
                af[0] = lds32(a0b + 192 * mt);
                af[1] = lds32(a0b + 192 * mt + 96);
                af[2] = lds32(a2b + 192 * mt);
                af[3] = lds32(a2b + 192 * mt + 96);
#pragma unroll
                for (int nt = 0; nt < 4; nt++) mma_f16(acc[mt][nt], af, &bh[2 * nt]);
            }
        }
    }

    // epilogue: pixel p = bt*16384 + (yp+srow)*128 + x
    size_t pbase = (size_t)bt * 16384 + (size_t)(yp + srow) * 128;
    int xrow = (wm & 1) * 64 + (lane >> 2);
    int cbase = wn * 32 + 2 * (lane & 3);
#pragma unroll
    for (int mt = 0; mt < 4; mt++) {
#pragma unroll
        for (int nt = 0; nt < 4; nt++) {
            int col = cbase + nt * 8;
            float b0 = s_bias[col], b1 = s_bias[col + 1];
            size_t r0 = (pbase + xrow + mt * 16) * 64 + col;
            size_t r1 = (pbase + xrow + mt * 16 + 8) * 64 + col;
            float a0 = fmaxf(acc[mt][nt][0] + b0, 0.f);
            float a1 = fmaxf(acc[mt][nt][1] + b1, 0.f);
            float a2 = fmaxf(acc[mt][nt][2] + b0, 0.f);
            float a3 = fmaxf(acc[mt][nt][3] + b1, 0.f);
            *reinterpret_cast<uint32_t*>(g_f1 + r0) = packh2(a0, a1);
            *reinterpret_cast<uint32_t*>(g_f1 + r1) = packh2(a2, a3);
        }
    }
}

// ---------------------------------------------------------------------------
// Implicit-GEMM 3x3 s2 conv, fp16 single-pass, 4-stage cp.async pipeline.
// Block tile 128 x 128, K chunk 32, 8 warps (2M x 4N).
// ---------------------------------------------------------------------------
template <int CIN, int COUT, int HIN, int WIN, int HOUT, int WOUT>
__global__ void __launch_bounds__(256, 2) conv_mma_kernel(
    const __half* __restrict__ in,
    const __half* __restrict__ wth,
    const float* __restrict__ bias,
    __half* __restrict__ outh)
{
    extern __shared__ char sm[];
    __shared__ float s_bias[128];

    const int KTOT = 9 * CIN;
    const int CPP  = CIN / 32;
    const int NT   = 9 * CPP;

    int tid  = threadIdx.x;
    int lane = tid & 31;
    int wid  = tid >> 5;
    int wm   = wid & 1;
    int wn   = wid >> 1;
    int cobase = blockIdx.y * 128;

    if (tid < 128) s_bias[tid] = bias[cobase + tid];

    int fr = tid >> 1;
    int fo = (tid & 1) * 16;
    int p  = blockIdx.x * 128 + fr;
    int fx = p % WOUT;
    int fy = (p / WOUT) % HOUT;
    int fbt = p / (WOUT * HOUT);
    const __half* bsh = wth + (size_t)(cobase + fr) * KTOT + fo;

    uint32_t smb = smem_u32(sm);

    int aoff = ((((lane >> 3) & 1) * 8 + (lane & 7)) * RS) + ((lane >> 4) * 8) * 2;
    int boff = (((lane >> 4) * 8 + (lane & 7)) * RS) + (((lane >> 3) & 1) * 8) * 2;

    float acc[4][4][4];
#pragma unroll
    for (int i = 0; i < 4; i++)
#pragma unroll
        for (int j = 0; j < 4; j++)
#pragma unroll
            for (int k = 0; k < 4; k++) acc[i][j][k] = 0.0f;

    auto FILL = [&](int s, int kt) {
        int pos = kt / CPP, ci0 = (kt - pos * CPP) * 32;
        int dy = pos / 3, dx = pos - dy * 3;
        int iy = 2 * fy + dy, ix = 2 * fx + dx;
        bool valid = (iy < HIN) && (ix < WIN);
        uint32_t vs = valid ? 16u : 0u;
        size_t asrc = valid
            ? ((((size_t)fbt * HIN + iy) * WIN + ix) * CIN + ci0 + fo) : 0;
        uint32_t d = smb + s * STG2 + fr * RS + fo * 2;
        cp16(d,             in + asrc,         vs);
        cp16(d + 16,        in + asrc + 8,     vs);
        cp16(d + MATB,      bsh + kt * 32,     16u);
        cp16(d + MATB + 16, bsh + kt * 32 + 8, 16u);
    };

    auto COMPUTE = [&](int s) {
        uint32_t ab = smb + s * STG2;
#pragma unroll
        for (int ks = 0; ks < 2; ks++) {
            uint32_t bh[8];
#pragma unroll
            for (int q = 0; q < 2; q++) {
                uint32_t ro = boff + (wn * 32 + q * 16) * RS + ks * 32;
                ldmx4(&bh[4 * q], ab + MATB + ro);
            }
#pragma unroll
            for (int mt = 0; mt < 4; mt++) {
                uint32_t af[4];
                ldmx4(af, ab + aoff + (wm * 64 + mt * 16) * RS + ks * 32);
#pragma unroll
                for (int nt = 0; nt < 4; nt++) mma_f16(acc[mt][nt], af, &bh[2 * nt]);
            }
        }
    };

    FILL(0, 0); CP_COMMIT();
    FILL(1, 1); CP_COMMIT();
    FILL(2, 2); CP_COMMIT();
#pragma unroll 1
    for (int kt = 0; kt < NT; kt++) {
        if (kt + 2 < NT)      { CP_WAIT2(); }
        else if (kt + 1 < NT) { CP_WAIT1(); }
        else                  { CP_WAIT0(); }
        __syncthreads();
        if (kt + 3 < NT) { FILL((kt + 3) & 3, kt + 3); CP_COMMIT(); }
        COMPUTE(kt & 3);
    }

    int mrow = blockIdx.x * 128 + wm * 64 + (lane >> 2);
    int cbase = wn * 32 + 2 * (lane & 3);
#pragma unroll
    for (int mt = 0; mt < 4; mt++) {
#pragma unroll
        for (int nt = 0; nt < 4; nt++) {
            int col = cbase + nt * 8;
            float b0 = s_bias[col], b1 = s_bias[col + 1];
            size_t r0 = (size_t)(mrow + mt * 16) * COUT + cobase + col;
            size_t r1 = (size_t)(mrow + mt * 16 + 8) * COUT + cobase + col;
            float a0 = fmaxf(acc[mt][nt][0] + b0, 0.f);
            float a1 = fmaxf(acc[mt][nt][1] + b1, 0.f);
            float a2 = fmaxf(acc[mt][nt][2] + b0, 0.f);
            float a3 = fmaxf(acc[mt][nt][3] + b1, 0.f);
            *reinterpret_cast<uint32_t*>(outh + r0) = packh2(a0, a1);
            *reinterpret_cast<uint32_t*>(outh + r1) = packh2(a2, a3);
        }
    }
}

// ---------------------------------------------------------------------------
// corr GEMM: D = Q . X^T / 16; fp16 in/out, 4-stage pipeline.
// ---------------------------------------------------------------------------
__global__ void __launch_bounds__(256, 2) corr_mma_kernel()
{
    extern __shared__ char sm[];

    int tid  = threadIdx.x;
    int lane = tid & 31;
    int wid  = tid >> 5;
    int wm   = wid & 1;
    int wn   = wid >> 1;

    int bt  = blockIdx.z;
    int b   = bt / 24;
    int n0  = blockIdx.y * 128;
    int hw0 = blockIdx.x * 128;

    int fr = tid >> 1;
    int fo = (tid & 1) * 16;
    const __half* ah = g_qh + ((size_t)b * 512 + n0 + fr) * 256 + fo;
    const __half* bx = g_f3 + ((size_t)bt * 1024 + hw0 + fr) * 256 + fo;

    uint32_t smb = smem_u32(sm);

    int aoff = ((((lane >> 3) & 1) * 8 + (lane & 7)) * RS) + ((lane >> 4) * 8) * 2;
    int boff = (((lane >> 4) * 8 + (lane & 7)) * RS) + (((lane >> 3) & 1) * 8) * 2;

    float acc[4][4][4];
#pragma unroll
    for (int i = 0; i < 4; i++)
#pragma unroll
        for (int j = 0; j < 4; j++)
#pragma unroll
            for (int k = 0; k < 4; k++) acc[i][j][k] = 0.0f;

    auto FILL = [&](int s, int kt) {
        uint32_t d = smb + s * STG2 + fr * RS + fo * 2;
        cp16(d,             ah + kt * 32,     16u);
        cp16(d + 16,        ah + kt * 32 + 8, 16u);
        cp16(d + MATB,      bx + kt * 32,     16u);
        cp16(d + MATB + 16, bx + kt * 32 + 8, 16u);
    };

    auto COMPUTE = [&](int s) {
        uint32_t ab = smb + s * STG2;
#pragma unroll
        for (int ks = 0; ks < 2; ks++) {
            uint32_t bxr[8];
#pragma unroll
            for (int q = 0; q < 2; q++) {
                uint32_t ro = boff + (wn * 32 + q * 16) * RS + ks * 32;
                ldmx4(&bxr[4 * q], ab + MATB + ro);
            }
#pragma unroll
            for (int mt = 0; mt < 4; mt++) {
                uint32_t af[4];
                ldmx4(af, ab + aoff + (wm * 64 + mt * 16) * RS + ks * 32);
#pragma unroll
                for (int nt = 0; nt < 4; nt++) mma_f16(acc[mt][nt], af, &bxr[2 * nt]);
            }
        }
    };

    FILL(0, 0); CP_COMMIT();
    FILL(1, 1); CP_COMMIT();
    FILL(2, 2); CP_COMMIT();
#pragma unroll 1
    for (int kt = 0; kt < 8; kt++) {
        if (kt + 2 < 8)      { CP_WAIT2(); }
        else if (kt + 1 < 8) { CP_WAIT1(); }
        else                 { CP_WAIT0(); }
        __syncthreads();
        if (kt + 3 < 8) { FILL((kt + 3) & 3, kt + 3); CP_COMMIT(); }
        COMPUTE(kt & 3);
    }

    __half* C = g_corrh + (size_t)bt * 512 * 1024;
    int mrow = n0 + wm * 64 + (lane >> 2);
    int cbase = hw0 + wn * 32 + 2 * (lane & 3);
#pragma unroll
    for (int mt = 0; mt < 4; mt++) {
#pragma unroll
        for (int nt = 0; nt < 4; nt++) {
            int col = cbase + nt * 8;
            int r0 = mrow + mt * 16;
            *reinterpret_cast<uint32_t*>(C + (size_t)r0 * 1024 + col) =
                packh2(acc[mt][nt][0] * 0.0625f, acc[mt][nt][1] * 0.0625f);
            *reinterpret_cast<uint32_t*>(C + (size_t)(r0 + 8) * 1024 + col) =
                packh2(acc[mt][nt][2] * 0.0625f, acc[mt][nt][3] * 0.0625f);
        }
    }
}

// ---------------------------------------------------------------------------
// Bilinear sampling from fp16 feat3 -> q fp16
// ---------------------------------------------------------------------------
__global__ void __launch_bounds__(256) sample_kernel(const float* __restrict__ qp)
{
    int bn = blockIdx.x;
    float q0 = qp[bn * 3 + 0];
    float q1 = qp[bn * 3 + 1];
    float q2 = qp[bn * 3 + 2];

    int t = (int)(q0 * 23.0f);
    t = min(max(t, 0), 23);
    float yf = q1 * 31.0f;
    float xf = q2 * 31.0f;
    int y0 = min(max((int)floorf(yf), 0), 31);
    int y1 = min(y0 + 1, 31);
    int x0 = min(max((int)floorf(xf), 0), 31);
    int x1 = min(x0 + 1, 31);
    float wy1 = yf - (float)y0, wy0 = 1.0f - wy1;
    float wx1 = xf - (float)x0, wx0 = 1.0f - wx1;

    int b = bn >> 9;
    const __half* f = g_f3 + (size_t)(b * 24 + t) * 1024 * 256;
    int c = threadIdx.x;
    float f00 = __half2float(f[(size_t)(y0 * 32 + x0) * 256 + c]);
    float f01 = __half2float(f[(size_t)(y0 * 32 + x1) * 256 + c]);
    float f10 = __half2float(f[(size_t)(y1 * 32 + x0) * 256 + c]);
    float f11 = __half2float(f[(size_t)(y1 * 32 + x1) * 256 + c]);
    float f0 = f00 * wx0 + f01 * wx1;
    float f1 = f10 * wx0 + f11 * wx1;
    float v = f0 * wy0 + f1 * wy1;
    g_qh[(size_t)bn * 256 + c] = __float2half(v);
}

// ---------------------------------------------------------------------------
// Fused softmax(corr*10) expectation + occlusion (fp16 corr input).
// ---------------------------------------------------------------------------
__global__ void __launch_bounds__(256) finalize_kernel(float* __restrict__ out)
{
    int gwarp = (blockIdx.x * 256 + threadIdx.x) >> 5;
    int lane  = threadIdx.x & 31;

    const __half* c = g_corrh + (size_t)gwarp * 1024;
    float v[32];
    float m = -1e30f;
#pragma unroll
    for (int i = 0; i < 4; i++) {
        uint4 t4 = *reinterpret_cast<const uint4*>(c + i * 256 + lane * 8);
        const uint32_t w[4] = {t4.x, t4.y, t4.z, t4.w};
#pragma unroll
        for (int q = 0; q < 4; q++) {
            __half2 h2 = *reinterpret_cast<const __half2*>(&w[q]);
            float f0 = __half2float(h2.x);
            float f1 = __half2float(h2.y);
            v[i * 8 + 2 * q + 0] = f0;
            v[i * 8 + 2 * q + 1] = f1;
            m = fmaxf(m, fmaxf(f0, f1));
        }
    }
#pragma unroll
    for (int o = 16; o > 0; o >>= 1)
        m = fmaxf(m, __shfl_xor_sync(0xffffffffu, m, o));

    float s = 0.0f, sx = 0.0f, sy = 0.0f;
#pragma unroll
    for (int i = 0; i < 4; i++) {
#pragma unroll
        for (int j = 0; j < 8; j++) {
            int idx = i * 256 + lane * 8 + j;
            float e = __expf(10.0f * (v[i * 8 + j] - m));
            s  += e;
            sx += e * (float)(idx & 31);
            sy += e * (float)(idx >> 5);
        }
    }
#pragma unroll
    for (int o = 16; o > 0; o >>= 1) {
        s  += __shfl_xor_sync(0xffffffffu, s, o);
        sx += __shfl_xor_sync(0xffffffffu, sx, o);
        sy += __shfl_xor_sync(0xffffffffu, sy, o);
    }

    if (lane == 0) {
        int bt = gwarp >> 9;
        int n  = gwarp & 511;
        int b  = bt / 24;
        int t  = bt - b * 24;
        int o  = (b * 512 + n) * 24 + t;
        float inv = 8.0f / s;
        out[2 * o + 0] = sx * inv;
        out[2 * o + 1] = sy * inv;
        out[2 * 24576 + o] = 1.0f / (1.0f + __expf(m));
    }
}

// ---------------------------------------------------------------------------
// Launch
// ---------------------------------------------------------------------------
extern "C" void kernel_launch(void* const* d_in, const int* in_sizes, int n_in,
                              void* d_out, int out_size)
{
    const float* video = (const float*)d_in[0];
    const float* qp    = (const float*)d_in[1];
    const float* w1    = (const float*)d_in[2];
    const float* b1    = (const float*)d_in[3];
    const float* w2    = (const float*)d_in[4];
    const float* b2    = (const float*)d_in[5];
    const float* w3    = (const float*)d_in[6];
    const float* b3    = (const float*)d_in[7];

    __half *f1, *f2, *f3, *wt2h, *wt3h;
    cudaGetSymbolAddress((void**)&f1, g_f1);
    cudaGetSymbolAddress((void**)&f2, g_f2);
    cudaGetSymbolAddress((void**)&f3, g_f3);
    cudaGetSymbolAddress((void**)&wt2h, g_w2h);
    cudaGetSymbolAddress((void**)&wt3h, g_w3h);

    cudaFuncSetAttribute((const void*)conv1_fused_kernel,
                         cudaFuncAttributeMaxDynamicSharedMemorySize, DSMEM_C1);
    cudaFuncSetAttribute(
        (const void*)conv_mma_kernel<64, 128, 128, 128, 64, 64>,
        cudaFuncAttributeMaxDynamicSharedMemorySize, DSMEM_CONV);
    cudaFuncSetAttribute(
        (const void*)conv_mma_kernel<128, 256, 64, 64, 32, 32>,
        cudaFuncAttributeMaxDynamicSharedMemorySize, DSMEM_CONV);
    cudaFuncSetAttribute((const void*)corr_mma_kernel,
                         cudaFuncAttributeMaxDynamicSharedMemorySize, DSMEM_CONV);

    // weight prep (tiny)
    prep_w1_kernel<<<40, 256>>>(w1);
    transpose_w<<<(576 * 128 + 255) / 256, 256>>>(w2, wt2h, 576, 128);
    transpose_w<<<(1152 * 256 + 255) / 256, 256>>>(w3, wt3h, 1152, 256);

    // conv1 fused v5: one block per (bt, row-pair)
    conv1_fused_kernel<<<48 * 64, 256, DSMEM_C1>>>(video, b1);

    // conv2: 196608 px / 128 = 1536 tiles
    conv_mma_kernel<64, 128, 128, 128, 64, 64>
        <<<dim3(1536, 1, 1), 256, DSMEM_CONV>>>(f1, wt2h, b2, f2);

    // conv3: 384 tiles x 2 N-chunks
    conv_mma_kernel<128, 256, 64, 64, 32, 32>
        <<<dim3(384, 2, 1), 256, DSMEM_CONV>>>(f2, wt3h, b3, f3);

    // sampling -> q fp16
    sample_kernel<<<1024, 256>>>(qp);

    // corr GEMM -> fp16 corr
    corr_mma_kernel<<<dim3(8, 4, 48), 256, DSMEM_CONV>>>();

    // softmax + expectation + occlusion
    finalize_kernel<<<3072, 256>>>((float*)d_out);
}

// round 15
// speedup vs baseline: 1.0169x; 1.0169x over previous
#include <cuda_runtime.h>
#include <cuda_fp16.h>
#include <math.h>
#include <stdint.h>

// ---------------------------------------------------------------------------
// B=2, T=24, H=256, W=256, N=512, HIDDEN=256
// conv1: fused, direct-LDS A, dense K=160, 2 output rows/block (R14 v5)
// conv2: 3x3x64->128 s2  implicit GEMM mma fp16, 3-stage pipeline (R13)
// conv3: 3x3x128->256 s2 implicit GEMM mma fp16, 3-stage pipeline (R13)
// corr : [48] 512x1024x256 GEMM mma fp16 -> corr fp16 (R13)
// ---------------------------------------------------------------------------

__device__ __half g_f1[2 * 24 * 128 * 128 * 64];          // 100 MB
__device__ __half g_f2[2 * 24 * 64 * 64 * 128];           //  50 MB
__device__ __half g_f3[2 * 24 * 32 * 32 * 256];           //  25 MB
__device__ __half g_qh[2 * 512 * 256];
__device__ __half g_corrh[2 * 24 * 512 * 1024];           //  50 MB (fp16 corr)
__device__ __half g_w1h[64 * 160];                        // conv1 W [cout][160]
__device__ __half g_w2h[128 * 576];
__device__ __half g_w3h[256 * 1152];

// ---------------------------------------------------------------------------
// helpers
// ---------------------------------------------------------------------------
__device__ __forceinline__ uint32_t smem_u32(const void* p) {
    uint32_t a;
    asm("{ .reg .u64 t; cvta.to.shared.u64 t, %1; cvt.u32.u64 %0, t; }"
        : "=r"(a) : "l"(p));
    return a;
}

__device__ __forceinline__ void cp16(uint32_t dst, const void* gsrc, uint32_t ss) {
    asm volatile(
        "{ .reg .u64 g; cvta.to.global.u64 g, %1;"
        "  cp.async.ca.shared.global [%0], [g], 16, %2; }"
        :: "r"(dst), "l"(gsrc), "r"(ss) : "memory");
}
#define CP_COMMIT() asm volatile("cp.async.commit_group;" ::: "memory")
#define CP_WAIT1()  asm volatile("cp.async.wait_group 1;" ::: "memory")
#define CP_WAIT0()  asm volatile("cp.async.wait_group 0;" ::: "memory")

__device__ __forceinline__ void ldmx4(uint32_t* r, uint32_t addr) {
    asm volatile(
        "ldmatrix.sync.aligned.m8n8.x4.shared.b16 {%0,%1,%2,%3}, [%4];"
        : "=r"(r[0]), "=r"(r[1]), "=r"(r[2]), "=r"(r[3]) : "r"(addr));
}

__device__ __forceinline__ uint32_t lds32(uint32_t addr) {
    uint32_t v;
    asm volatile("ld.shared.b32 %0, [%1];" : "=r"(v) : "r"(addr));
    return v;
}

__device__ __forceinline__ void mma_f16(float* d, const uint32_t* a,
                                        const uint32_t* b) {
    asm volatile(
        "mma.sync.aligned.m16n8k16.row.col.f32.f16.f16.f32 "
        "{%0,%1,%2,%3}, {%4,%5,%6,%7}, {%8,%9}, {%0,%1,%2,%3};"
        : "+f"(d[0]), "+f"(d[1]), "+f"(d[2]), "+f"(d[3])
        : "r"(a[0]), "r"(a[1]), "r"(a[2]), "r"(a[3]), "r"(b[0]), "r"(b[1]));
}

__device__ __forceinline__ uint32_t packh2(float a, float b) {
    __half2 t = __floats2half2_rn(a, b);
    return *reinterpret_cast<uint32_t*>(&t);
}

// smem tile: rows x 32 fp16, row stride 80 B (16B pad, conflict-free ldmatrix)
#define RS    80
#define MATB  (128 * RS)            // 10240 B (128-row tile)
#define STG2  (2 * MATB)            // A | B (single-pass)
#define DSMEM_CONV (3 * STG2)       // 61440 B, 3-stage pipeline

// conv1 v5 (2 rows/block): B (5 chunks x 64 rows x RS) + V (10 rows)
#define C1_B    0
#define C1_V    (5 * 64 * RS)             // 25600
#define C1_VROW 1600
#define DSMEM_C1 (C1_V + 10 * C1_VROW)    // 41600

// ---------------------------------------------------------------------------
// conv1 weight prep: dense-K layout. k = dy*22 + r, r = dx*3+ci (r<21),
// zero at r=21 and k>=154.
// ---------------------------------------------------------------------------
__global__ void __launch_bounds__(256) prep_w1_kernel(const float* __restrict__ w)
{
    int i = blockIdx.x * 256 + threadIdx.x;   // 64*160
    if (i >= 64 * 160) return;
    int c = i / 160, kk = i - c * 160;
    int dy = kk / 22, r = kk - dy * 22;
    float v = (dy < 7 && r < 21) ? w[(dy * 21 + r) * 64 + c] : 0.f;
    g_w1h[i] = __float2half(v);
}

// w[k][cout] -> wt[cout][k] fp16
__global__ void __launch_bounds__(256) transpose_w(
    const float* __restrict__ w, __half* __restrict__ h, int K, int C)
{
    int i = blockIdx.x * 256 + threadIdx.x;
    if (i < K * C) {
        int k = i / C, c = i - k * C;
        h[(size_t)c * K + k] = __float2half(w[i]);
    }
}

// ---------------------------------------------------------------------------
// conv1 fused v5: one block = TWO output rows (bt, yp..yp+1) = 256 px (M).
// Tile rows [0,128) = output row yp, [128,256) = yp+1 (srow = wm>>1).
// A[x][dy*22+r] = vsm[dy + 2*srow][6x + r]; dy==7 (pad) -> zero row 9.
// K = 160 (5 chunks). No A staging, no mainloop syncs.
// ---------------------------------------------------------------------------
__global__ void __launch_bounds__(256, 2) conv1_fused_kernel(
    const float* __restrict__ video,
    const float* __restrict__ bias)
{
    extern __shared__ char sm[];
    __shared__ float s_bias[64];

    int tid  = threadIdx.x;
    int lane = tid & 31;
    int wid  = tid >> 5;
    int wm   = wid & 3;          // 4 M-warps (64 rows each)
    int wn   = wid >> 2;         // 2 N-warps (32 cols each)

    int yp = (blockIdx.x & 63) * 2;
    int bt = blockIdx.x >> 6;

    if (tid < 64) s_bias[tid] = bias[tid];

    uint32_t smb = smem_u32(sm);

    // B preload: 5 chunks x 64 rows x 4 segs = 1280 cp16
    for (int u = tid; u < 1280; u += 256) {
        int seg = u & 3;
        int cc  = (u >> 2) % 5;
        int r   = u / 20;
        const __half* s = g_w1h + r * 160 + cc * 32 + seg * 8;
        uint32_t d = smb + C1_B + (cc * 64 + r) * RS + seg * 16;
        cp16(d, s, 16u);
    }
    CP_COMMIT();

    // zero video smem: 10 rows (9 video + zero row 9)
    uint32_t* vz = reinterpret_cast<uint32_t*>(sm + C1_V);
    for (int u = tid; u < 10 * C1_VROW / 4; u += 256) vz[u] = 0u;
    __syncthreads();

    // video rows j=0..8: iy = 2*yp + j - 2; 768 floats -> halfs slot [6..773]
    const float inv255 = 1.0f / 255.0f;
    for (int u = tid; u < 9 * 384; u += 256) {
        int j = u / 384;
        int m = u - j * 384;
        int iy = 2 * yp + j - 2;
        if ((unsigned)iy < 256u) {
            const float2 v2 = *reinterpret_cast<const float2*>(
                video + ((size_t)(bt * 256 + iy) * 256) * 3 + 2 * m);
            uint32_t pk = packh2(v2.x * inv255, v2.y * inv255);
            *reinterpret_cast<uint32_t*>(sm + C1_V + j * C1_VROW + 12 + 4 * m) = pk;
        }
    }
    CP_WAIT0();
    __syncthreads();

    int srow = wm >> 1;
    uint32_t xb0 = 12u * ((wm & 1) * 64 + (lane >> 2));   // 6x * 2 bytes
    int klane = 2 * (lane & 3);

    int boff = (((lane >> 4) * 8 + (lane & 7)) * RS) + (((lane >> 3) & 1) * 8) * 2;

    float acc[4][4][4];
#pragma unroll
    for (int i = 0; i < 4; i++)
#pragma unroll
        for (int j = 0; j < 4; j++)
#pragma unroll
            for (int k = 0; k < 4; k++) acc[i][j][k] = 0.0f;

    // sync-free mainloop: 5 chunks x 2 ks, 4 M-tiles each
#pragma unroll
    for (int cc = 0; cc < 5; cc++) {
        uint32_t bb = smb + C1_B + cc * (64 * RS);
#pragma unroll
        for (int ks = 0; ks < 2; ks++) {
            uint32_t bh[8];
#pragma unroll
            for (int q = 0; q < 2; q++) {
                uint32_t ro = boff + (wn * 32 + q * 16) * RS + ks * 32;
                ldmx4(&bh[4 * q], bb + ro);
            }
            int k0  = cc * 32 + ks * 16 + klane;
            int dy0 = k0 / 22, r0 = k0 - 22 * dy0;
            int k2  = k0 + 8;
            int dy2 = k2 / 22, r2 = k2 - 22 * dy2;
            int j0 = (dy0 < 7) ? (dy0 + 2 * srow) : 9;
            int j2 = (dy2 < 7) ? (dy2 + 2 * srow) : 9;
            uint32_t a0b = smb + C1_V + j0 * C1_VROW + r0 * 2 + xb0;
            uint32_t a2b = smb + C1_V + j2 * C1_VROW + r2 * 2 + xb0;
#pragma unroll
            for (int mt = 0; mt < 4; mt++) {
                uint32_t af[4];
                af[0] = lds32(a0b + 192 * mt);
                af[1] = lds32(a0b + 192 * mt + 96);
                af[2] = lds32(a2b + 192 * mt);
                af[3] = lds32(a2b + 192 * mt + 96);
#pragma unroll
                for (int nt = 0; nt < 4; nt++) mma_f16(acc[mt][nt], af, &bh[2 * nt]);
            }
        }
    }

    // epilogue: pixel p = bt*16384 + (yp+srow)*128 + x
    size_t pbase = (size_t)bt * 16384 + (size_t)(yp + srow) * 128;
    int xrow = (wm & 1) * 64 + (lane >> 2);
    int cbase = wn * 32 + 2 * (lane & 3);
#pragma unroll
    for (int mt = 0; mt < 4; mt++) {
#pragma unroll
        for (int nt = 0; nt < 4; nt++) {
            int col = cbase + nt * 8;
            float b0 = s_bias[col], b1 = s_bias[col + 1];
            size_t r0 = (pbase + xrow + mt * 16) * 64 + col;
            size_t r1 = (pbase + xrow + mt * 16 + 8) * 64 + col;
            float a0 = fmaxf(acc[mt][nt][0] + b0, 0.f);
            float a1 = fmaxf(acc[mt][nt][1] + b1, 0.f);
            float a2 = fmaxf(acc[mt][nt][2] + b0, 0.f);
            float a3 = fmaxf(acc[mt][nt][3] + b1, 0.f);
            *reinterpret_cast<uint32_t*>(g_f1 + r0) = packh2(a0, a1);
            *reinterpret_cast<uint32_t*>(g_f1 + r1) = packh2(a2, a3);
        }
    }
}

// ---------------------------------------------------------------------------
// Implicit-GEMM 3x3 s2 conv, fp16 single-pass, 3-stage cp.async pipeline.
// Block tile 128 x 128, K chunk 32, 8 warps (2M x 4N).
// ---------------------------------------------------------------------------
template <int CIN, int COUT, int HIN, int WIN, int HOUT, int WOUT>
__global__ void __launch_bounds__(256, 2) conv_mma_kernel(
    const __half* __restrict__ in,
    const __half* __restrict__ wth,
    const float* __restrict__ bias,
    __half* __restrict__ outh)
{
    extern __shared__ char sm[];
    __shared__ float s_bias[128];

    const int KTOT = 9 * CIN;
    const int CPP  = CIN / 32;
    const int NT   = 9 * CPP;

    int tid  = threadIdx.x;
    int lane = tid & 31;
    int wid  = tid >> 5;
    int wm   = wid & 1;
    int wn   = wid >> 1;
    int cobase = blockIdx.y * 128;

    if (tid < 128) s_bias[tid] = bias[cobase + tid];

    int fr = tid >> 1;
    int fo = (tid & 1) * 16;
    int p  = blockIdx.x * 128 + fr;
    int fx = p % WOUT;
    int fy = (p / WOUT) % HOUT;
    int fbt = p / (WOUT * HOUT);
    const __half* bsh = wth + (size_t)(cobase + fr) * KTOT + fo;

    uint32_t smb = smem_u32(sm);

    int aoff = ((((lane >> 3) & 1) * 8 + (lane & 7)) * RS) + ((lane >> 4) * 8) * 2;
    int boff = (((lane >> 4) * 8 + (lane & 7)) * RS) + (((lane >> 3) & 1) * 8) * 2;

    float acc[4][4][4];
#pragma unroll
    for (int i = 0; i < 4; i++)
#pragma unroll
        for (int j = 0; j < 4; j++)
#pragma unroll
            for (int k = 0; k < 4; k++) acc[i][j][k] = 0.0f;

    auto FILL = [&](int s, int kt) {
        int pos = kt / CPP, ci0 = (kt - pos * CPP) * 32;
        int dy = pos / 3, dx = pos - dy * 3;
        int iy = 2 * fy + dy, ix = 2 * fx + dx;
        bool valid = (iy < HIN) && (ix < WIN);
        uint32_t vs = valid ? 16u : 0u;
        size_t asrc = valid
            ? ((((size_t)fbt * HIN + iy) * WIN + ix) * CIN + ci0 + fo) : 0;
        uint32_t d = smb + s * STG2 + fr * RS + fo * 2;
        cp16(d,             in + asrc,         vs);
        cp16(d + 16,        in + asrc + 8,     vs);
        cp16(d + MATB,      bsh + kt * 32,     16u);
        cp16(d + MATB + 16, bsh + kt * 32 + 8, 16u);
    };

    auto COMPUTE = [&](int s) {
        uint32_t ab = smb + s * STG2;
#pragma unroll
        for (int ks = 0; ks < 2; ks++) {
            uint32_t bh[8];
#pragma unroll
            for (int q = 0; q < 2; q++) {
                uint32_t ro = boff + (wn * 32 + q * 16) * RS + ks * 32;
                ldmx4(&bh[4 * q], ab + MATB + ro);
            }
#pragma unroll
            for (int mt = 0; mt < 4; mt++) {
                uint32_t af[4];
                ldmx4(af, ab + aoff + (wm * 64 + mt * 16) * RS + ks * 32);
#pragma unroll
                for (int nt = 0; nt < 4; nt++) mma_f16(acc[mt][nt], af, &bh[2 * nt]);
            }
        }
    };

    FILL(0, 0); CP_COMMIT();
    FILL(1, 1); CP_COMMIT();
#pragma unroll 1
    for (int kt = 0; kt < NT; kt++) {
        if (kt + 1 < NT) { CP_WAIT1(); } else { CP_WAIT0(); }
        __syncthreads();
        if (kt + 2 < NT) { FILL((kt + 2) % 3, kt + 2); CP_COMMIT(); }
        COMPUTE(kt % 3);
    }

    int mrow = blockIdx.x * 128 + wm * 64 + (lane >> 2);
    int cbase = wn * 32 + 2 * (lane & 3);
#pragma unroll
    for (int mt = 0; mt < 4; mt++) {
#pragma unroll
        for (int nt = 0; nt < 4; nt++) {
            int col = cbase + nt * 8;
            float b0 = s_bias[col], b1 = s_bias[col + 1];
            size_t r0 = (size_t)(mrow + mt * 16) * COUT + cobase + col;
            size_t r1 = (size_t)(mrow + mt * 16 + 8) * COUT + cobase + col;
            float a0 = fmaxf(acc[mt][nt][0] + b0, 0.f);
            float a1 = fmaxf(acc[mt][nt][1] + b1, 0.f);
            float a2 = fmaxf(acc[mt][nt][2] + b0, 0.f);
            float a3 = fmaxf(acc[mt][nt][3] + b1, 0.f);
            *reinterpret_cast<uint32_t*>(outh + r0) = packh2(a0, a1);
            *reinterpret_cast<uint32_t*>(outh + r1) = packh2(a2, a3);
        }
    }
}

// ---------------------------------------------------------------------------
// corr GEMM: D = Q . X^T / 16; fp16 in/out, 3-stage pipeline.
// ---------------------------------------------------------------------------
__global__ void __launch_bounds__(256, 2) corr_mma_kernel()
{
    extern __shared__ char sm[];

    int tid  = threadIdx.x;
    int lane = tid & 31;
    int wid  = tid >> 5;
    int wm   = wid & 1;
    int wn   = wid >> 1;

    int bt  = blockIdx.z;
    int b   = bt / 24;
    int n0  = blockIdx.y * 128;
    int hw0 = blockIdx.x * 128;

    int fr = tid >> 1;
    int fo = (tid & 1) * 16;
    const __half* ah = g_qh + ((size_t)b * 512 + n0 + fr) * 256 + fo;
    const __half* bx = g_f3 + ((size_t)bt * 1024 + hw0 + fr) * 256 + fo;

    uint32_t smb = smem_u32(sm);

    int aoff = ((((lane >> 3) & 1) * 8 + (lane & 7)) * RS) + ((lane >> 4) * 8) * 2;
    int boff = (((lane >> 4) * 8 + (lane & 7)) * RS) + (((lane >> 3) & 1) * 8) * 2;

    float acc[4][4][4];
#pragma unroll
    for (int i = 0; i < 4; i++)
#pragma unroll
        for (int j = 0; j < 4; j++)
#pragma unroll
            for (int k = 0; k < 4; k++) acc[i][j][k] = 0.0f;

    auto FILL = [&](int s, int kt) {
        uint32_t d = smb + s * STG2 + fr * RS + fo * 2;
        cp16(d,             ah + kt * 32,     16u);
        cp16(d + 16,        ah + kt * 32 + 8, 16u);
        cp16(d + MATB,      bx + kt * 32,     16u);
        cp16(d + MATB + 16, bx + kt * 32 + 8, 16u);
    };

    auto COMPUTE = [&](int s) {
        uint32_t ab = smb + s * STG2;
#pragma unroll
        for (int ks = 0; ks < 2; ks++) {
            uint32_t bxr[8];
#pragma unroll
            for (int q = 0; q < 2; q++) {
                uint32_t ro = boff + (wn * 32 + q * 16) * RS + ks * 32;
                ldmx4(&bxr[4 * q], ab + MATB + ro);
            }
#pragma unroll
            for (int mt = 0; mt < 4; mt++) {
                uint32_t af[4];
                ldmx4(af, ab + aoff + (wm * 64 + mt * 16) * RS + ks * 32);
#pragma unroll
                for (int nt = 0; nt < 4; nt++) mma_f16(acc[mt][nt], af, &bxr[2 * nt]);
            }
        }
    };

    FILL(0, 0); CP_COMMIT();
    FILL(1, 1); CP_COMMIT();
#pragma unroll 1
    for (int kt = 0; kt < 8; kt++) {
        if (kt + 1 < 8) { CP_WAIT1(); } else { CP_WAIT0(); }
        __syncthreads();
        if (kt + 2 < 8) { FILL((kt + 2) % 3, kt + 2); CP_COMMIT(); }
        COMPUTE(kt % 3);
    }

    __half* C = g_corrh + (size_t)bt * 512 * 1024;
    int mrow = n0 + wm * 64 + (lane >> 2);
    int cbase = hw0 + wn * 32 + 2 * (lane & 3);
#pragma unroll
    for (int mt = 0; mt < 4; mt++) {
#pragma unroll
        for (int nt = 0; nt < 4; nt++) {
            int col = cbase + nt * 8;
            int r0 = mrow + mt * 16;
            *reinterpret_cast<uint32_t*>(C + (size_t)r0 * 1024 + col) =
                packh2(acc[mt][nt][0] * 0.0625f, acc[mt][nt][1] * 0.0625f);
            *reinterpret_cast<uint32_t*>(C + (size_t)(r0 + 8) * 1024 + col) =
                packh2(acc[mt][nt][2] * 0.0625f, acc[mt][nt][3] * 0.0625f);
        }
    }
}

// ---------------------------------------------------------------------------
// Bilinear sampling from fp16 feat3 -> q fp16
// ---------------------------------------------------------------------------
__global__ void __launch_bounds__(256) sample_kernel(const float* __restrict__ qp)
{
    int bn = blockIdx.x;
    float q0 = qp[bn * 3 + 0];
    float q1 = qp[bn * 3 + 1];
    float q2 = qp[bn * 3 + 2];

    int t = (int)(q0 * 23.0f);
    t = min(max(t, 0), 23);
    float yf = q1 * 31.0f;
    float xf = q2 * 31.0f;
    int y0 = min(max((int)floorf(yf), 0), 31);
    int y1 = min(y0 + 1, 31);
    int x0 = min(max((int)floorf(xf), 0), 31);
    int x1 = min(x0 + 1, 31);
    float wy1 = yf - (float)y0, wy0 = 1.0f - wy1;
    float wx1 = xf - (float)x0, wx0 = 1.0f - wx1;

    int b = bn >> 9;
    const __half* f = g_f3 + (size_t)(b * 24 + t) * 1024 * 256;
    int c = threadIdx.x;
    float f00 = __half2float(f[(size_t)(y0 * 32 + x0) * 256 + c]);
    float f01 = __half2float(f[(size_t)(y0 * 32 + x1) * 256 + c]);
    float f10 = __half2float(f[(size_t)(y1 * 32 + x0) * 256 + c]);
    float f11 = __half2float(f[(size_t)(y1 * 32 + x1) * 256 + c]);
    float f0 = f00 * wx0 + f01 * wx1;
    float f1 = f10 * wx0 + f11 * wx1;
    float v = f0 * wy0 + f1 * wy1;
    g_qh[(size_t)bn * 256 + c] = __float2half(v);
}

// ---------------------------------------------------------------------------
// Fused softmax(corr*10) expectation + occlusion (fp16 corr input).
// ---------------------------------------------------------------------------
__global__ void __launch_bounds__(256) finalize_kernel(float* __restrict__ out)
{
    int gwarp = (blockIdx.x * 256 + threadIdx.x) >> 5;
    int lane  = threadIdx.x & 31;

    const __half* c = g_corrh + (size_t)gwarp * 1024;
    float v[32];
    float m = -1e30f;
#pragma unroll
    for (int i = 0; i < 4; i++) {
        uint4 t4 = *reinterpret_cast<const uint4*>(c + i * 256 + lane * 8);
        const uint32_t w[4] = {t4.x, t4.y, t4.z, t4.w};
#pragma unroll
        for (int q = 0; q < 4; q++) {
            __half2 h2 = *reinterpret_cast<const __half2*>(&w[q]);
            float f0 = __half2float(h2.x);
            float f1 = __half2float(h2.y);
            v[i * 8 + 2 * q + 0] = f0;
            v[i * 8 + 2 * q + 1] = f1;
            m = fmaxf(m, fmaxf(f0, f1));
        }
    }
#pragma unroll
    for (int o = 16; o > 0; o >>= 1)
        m = fmaxf(m, __shfl_xor_sync(0xffffffffu, m, o));

    float s = 0.0f, sx = 0.0f, sy = 0.0f;
#pragma unroll
    for (int i = 0; i < 4; i++) {
#pragma unroll
        for (int j = 0; j < 8; j++) {
            int idx = i * 256 + lane * 8 + j;
            float e = __expf(10.0f * (v[i * 8 + j] - m));
            s  += e;
            sx += e * (float)(idx & 31);
            sy += e * (float)(idx >> 5);
        }
    }
#pragma unroll
    for (int o = 16; o > 0; o >>= 1) {
        s  += __shfl_xor_sync(0xffffffffu, s, o);
        sx += __shfl_xor_sync(0xffffffffu, sx, o);
        sy += __shfl_xor_sync(0xffffffffu, sy, o);
    }

    if (lane == 0) {
        int bt = gwarp >> 9;
        int n  = gwarp & 511;
        int b  = bt / 24;
        int t  = bt - b * 24;
        int o  = (b * 512 + n) * 24 + t;
        float inv = 8.0f / s;
        out[2 * o + 0] = sx * inv;
        out[2 * o + 1] = sy * inv;
        out[2 * 24576 + o] = 1.0f / (1.0f + __expf(m));
    }
}

// ---------------------------------------------------------------------------
// Launch
// ---------------------------------------------------------------------------
extern "C" void kernel_launch(void* const* d_in, const int* in_sizes, int n_in,
                              void* d_out, int out_size)
{
    const float* video = (const float*)d_in[0];
    const float* qp    = (const float*)d_in[1];
    const float* w1    = (const float*)d_in[2];
    const float* b1    = (const float*)d_in[3];
    const float* w2    = (const float*)d_in[4];
    const float* b2    = (const float*)d_in[5];
    const float* w3    = (const float*)d_in[6];
    const float* b3    = (const float*)d_in[7];

    __half *f1, *f2, *f3, *wt2h, *wt3h;
    cudaGetSymbolAddress((void**)&f1, g_f1);
    cudaGetSymbolAddress((void**)&f2, g_f2);
    cudaGetSymbolAddress((void**)&f3, g_f3);
    cudaGetSymbolAddress((void**)&wt2h, g_w2h);
    cudaGetSymbolAddress((void**)&wt3h, g_w3h);

    cudaFuncSetAttribute((const void*)conv1_fused_kernel,
                         cudaFuncAttributeMaxDynamicSharedMemorySize, DSMEM_C1);
    cudaFuncSetAttribute(
        (const void*)conv_mma_kernel<64, 128, 128, 128, 64, 64>,
        cudaFuncAttributeMaxDynamicSharedMemorySize, DSMEM_CONV);
    cudaFuncSetAttribute(
        (const void*)conv_mma_kernel<128, 256, 64, 64, 32, 32>,
        cudaFuncAttributeMaxDynamicSharedMemorySize, DSMEM_CONV);
    cudaFuncSetAttribute((const void*)corr_mma_kernel,
                         cudaFuncAttributeMaxDynamicSharedMemorySize, DSMEM_CONV);

    // weight prep (tiny)
    prep_w1_kernel<<<40, 256>>>(w1);
    transpose_w<<<(576 * 128 + 255) / 256, 256>>>(w2, wt2h, 576, 128);
    transpose_w<<<(1152 * 256 + 255) / 256, 256>>>(w3, wt3h, 1152, 256);

    // conv1 fused v5: one block per (bt, row-pair)
    conv1_fused_kernel<<<48 * 64, 256, DSMEM_C1>>>(video, b1);

    // conv2: 196608 px / 128 = 1536 tiles
    conv_mma_kernel<64, 128, 128, 128, 64, 64>
        <<<dim3(1536, 1, 1), 256, DSMEM_CONV>>>(f1, wt2h, b2, f2);

    // conv3: 384 tiles x 2 N-chunks
    conv_mma_kernel<128, 256, 64, 64, 32, 32>
        <<<dim3(384, 2, 1), 256, DSMEM_CONV>>>(f2, wt3h, b3, f3);

    // sampling -> q fp16
    sample_kernel<<<1024, 256>>>(qp);

    // corr GEMM -> fp16 corr
    corr_mma_kernel<<<dim3(8, 4, 48), 256, DSMEM_CONV>>>();

    // softmax + expectation + occlusion
    finalize_kernel<<<3072, 256>>>((float*)d_out);
}

// round 16
// speedup vs baseline: 1.0201x; 1.0031x over previous
#include <cuda_runtime.h>
#include <cuda_fp16.h>
#include <math.h>
#include <stdint.h>

// ---------------------------------------------------------------------------
// B=2, T=24, H=256, W=256, N=512, HIDDEN=256
// conv1: fused, direct-LDS A, dense K=160, 2 rows/block, 8Mx1N warps (v6)
// conv2: 3x3x64->128 s2  implicit GEMM mma fp16, 3-stage pipeline
// conv3: 3x3x128->256 s2 implicit GEMM mma fp16, 3-stage pipeline
// corr : [48] 512x1024x256 GEMM mma fp16 -> corr fp16
// ---------------------------------------------------------------------------

__device__ __half g_f1[2 * 24 * 128 * 128 * 64];          // 100 MB
__device__ __half g_f2[2 * 24 * 64 * 64 * 128];           //  50 MB
__device__ __half g_f3[2 * 24 * 32 * 32 * 256];           //  25 MB
__device__ __half g_qh[2 * 512 * 256];
__device__ __half g_corrh[2 * 24 * 512 * 1024];           //  50 MB (fp16 corr)
__device__ __half g_w1h[64 * 160];                        // conv1 W [cout][160]
__device__ __half g_w2h[128 * 576];
__device__ __half g_w3h[256 * 1152];

// ---------------------------------------------------------------------------
// helpers
// ---------------------------------------------------------------------------
__device__ __forceinline__ uint32_t smem_u32(const void* p) {
    uint32_t a;
    asm("{ .reg .u64 t; cvta.to.shared.u64 t, %1; cvt.u32.u64 %0, t; }"
        : "=r"(a) : "l"(p));
    return a;
}

__device__ __forceinline__ void cp16(uint32_t dst, const void* gsrc, uint32_t ss) {
    asm volatile(
        "{ .reg .u64 g; cvta.to.global.u64 g, %1;"
        "  cp.async.ca.shared.global [%0], [g], 16, %2; }"
        :: "r"(dst), "l"(gsrc), "r"(ss) : "memory");
}
#define CP_COMMIT() asm volatile("cp.async.commit_group;" ::: "memory")
#define CP_WAIT1()  asm volatile("cp.async.wait_group 1;" ::: "memory")
#define CP_WAIT0()  asm volatile("cp.async.wait_group 0;" ::: "memory")

__device__ __forceinline__ void ldmx4(uint32_t* r, uint32_t addr) {
    asm volatile(
        "ldmatrix.sync.aligned.m8n8.x4.shared.b16 {%0,%1,%2,%3}, [%4];"
        : "=r"(r[0]), "=r"(r[1]), "=r"(r[2]), "=r"(r[3]) : "r"(addr));
}

__device__ __forceinline__ uint32_t lds32(uint32_t addr) {
    uint32_t v;
    asm volatile("ld.shared.b32 %0, [%1];" : "=r"(v) : "r"(addr));
    return v;
}

__device__ __forceinline__ void mma_f16(float* d, const uint32_t* a,
                                        const uint32_t* b) {
    asm volatile(
        "mma.sync.aligned.m16n8k16.row.col.f32.f16.f16.f32 "
        "{%0,%1,%2,%3}, {%4,%5,%6,%7}, {%8,%9}, {%0,%1,%2,%3};"
        : "+f"(d[0]), "+f"(d[1]), "+f"(d[2]), "+f"(d[3])
        : "r"(a[0]), "r"(a[1]), "r"(a[2]), "r"(a[3]), "r"(b[0]), "r"(b[1]));
}

__device__ __forceinline__ uint32_t packh2(float a, float b) {
    __half2 t = __floats2half2_rn(a, b);
    return *reinterpret_cast<uint32_t*>(&t);
}

// smem tile: rows x 32 fp16, row stride 80 B (16B pad, conflict-free ldmatrix)
#define RS    80
#define MATB  (128 * RS)            // 10240 B (128-row tile)
#define STG2  (2 * MATB)            // A | B (single-pass)
#define DSMEM_CONV (3 * STG2)       // 61440 B, 3-stage pipeline

// conv1 (2 rows/block): B (5 chunks x 64 rows x RS) + V (10 rows)
#define C1_B    0
#define C1_V    (5 * 64 * RS)             // 25600
#define C1_VROW 1600
#define DSMEM_C1 (C1_V + 10 * C1_VROW)    // 41600

// ---------------------------------------------------------------------------
// conv1 weight prep: dense-K layout. k = dy*22 + r, r = dx*3+ci (r<21),
// zero at r=21 and k>=154.
// ---------------------------------------------------------------------------
__global__ void __launch_bounds__(256) prep_w1_kernel(const float* __restrict__ w)
{
    int i = blockIdx.x * 256 + threadIdx.x;   // 64*160
    if (i >= 64 * 160) return;
    int c = i / 160, kk = i - c * 160;
    int dy = kk / 22, r = kk - dy * 22;
    float v = (dy < 7 && r < 21) ? w[(dy * 21 + r) * 64 + c] : 0.f;
    g_w1h[i] = __float2half(v);
}

// w[k][cout] -> wt[cout][k] fp16
__global__ void __launch_bounds__(256) transpose_w(
    const float* __restrict__ w, __half* __restrict__ h, int K, int C)
{
    int i = blockIdx.x * 256 + threadIdx.x;
    if (i < K * C) {
        int k = i / C, c = i - k * C;
        h[(size_t)c * K + k] = __float2half(w[i]);
    }
}

// ---------------------------------------------------------------------------
// conv1 fused v6: one block = TWO output rows (bt, yp..yp+1) = 256 px (M).
// 8 warps = 8M x 1N: warp w covers rows [w*32, w*32+32) of the 256-row tile
// and ALL 64 cout columns (nt=0..7). srow = w>>2 selects output row.
// A fragments per-lane LDS.32 from staged video rows. K = 160 (5 chunks).
// ---------------------------------------------------------------------------
__global__ void __launch_bounds__(256, 2) conv1_fused_kernel(
    const float* __restrict__ video,
    const float* __restrict__ bias)
{
    extern __shared__ char sm[];
    __shared__ float s_bias[64];

    int tid  = threadIdx.x;
    int lane = tid & 31;
    int wid  = tid >> 5;

    int yp = (blockIdx.x & 63) * 2;
    int bt = blockIdx.x >> 6;

    if (tid < 64) s_bias[tid] = bias[tid];

    uint32_t smb = smem_u32(sm);

    // B preload: 5 chunks x 64 rows x 4 segs = 1280 cp16
    for (int u = tid; u < 1280; u += 256) {
        int seg = u & 3;
        int cc  = (u >> 2) % 5;
        int r   = u / 20;
        const __half* s = g_w1h + r * 160 + cc * 32 + seg * 8;
        uint32_t d = smb + C1_B + (cc * 64 + r) * RS + seg * 16;
        cp16(d, s, 16u);
    }
    CP_COMMIT();

    // zero video smem: 10 rows (9 video + zero row 9)
    uint32_t* vz = reinterpret_cast<uint32_t*>(sm + C1_V);
    for (int u = tid; u < 10 * C1_VROW / 4; u += 256) vz[u] = 0u;
    __syncthreads();

    // video rows j=0..8: iy = 2*yp + j - 2; 768 floats -> halfs slot [6..773]
    const float inv255 = 1.0f / 255.0f;
    for (int u = tid; u < 9 * 384; u += 256) {
        int j = u / 384;
        int m = u - j * 384;
        int iy = 2 * yp + j - 2;
        if ((unsigned)iy < 256u) {
            const float2 v2 = *reinterpret_cast<const float2*>(
                video + ((size_t)(bt * 256 + iy) * 256) * 3 + 2 * m);
            uint32_t pk = packh2(v2.x * inv255, v2.y * inv255);
            *reinterpret_cast<uint32_t*>(sm + C1_V + j * C1_VROW + 12 + 4 * m) = pk;
        }
    }
    CP_WAIT0();
    __syncthreads();

    int srow = wid >> 2;                              // output row select
    uint32_t xb0 = 12u * ((wid & 3) * 32 + (lane >> 2));   // 6x * 2 bytes
    int klane = 2 * (lane & 3);

    int boff = (((lane >> 4) * 8 + (lane & 7)) * RS) + (((lane >> 3) & 1) * 8) * 2;

    float acc[2][8][4];
#pragma unroll
    for (int i = 0; i < 2; i++)
#pragma unroll
        for (int j = 0; j < 8; j++)
#pragma unroll
            for (int k = 0; k < 4; k++) acc[i][j][k] = 0.0f;

    // sync-free mainloop: 5 chunks x 2 ks; per ks: 4 B-ldmatrix + 2x4 A-LDS
#pragma unroll
    for (int cc = 0; cc < 5; cc++) {
        uint32_t bb = smb + C1_B + cc * (64 * RS);
#pragma unroll
        for (int ks = 0; ks < 2; ks++) {
            uint32_t bh[16];
#pragma unroll
            for (int q = 0; q < 4; q++) {
                uint32_t ro = boff + (q * 16) * RS + ks * 32;
                ldmx4(&bh[4 * q], bb + ro);
            }
            int k0  = cc * 32 + ks * 16 + klane;
            int dy0 = k0 / 22, r0 = k0 - 22 * dy0;
            int k2  = k0 + 8;
            int dy2 = k2 / 22, r2 = k2 - 22 * dy2;
            int j0 = (dy0 < 7) ? (dy0 + 2 * srow) : 9;
            int j2 = (dy2 < 7) ? (dy2 + 2 * srow) : 9;
            uint32_t a0b = smb + C1_V + j0 * C1_VROW + r0 * 2 + xb0;
            uint32_t a2b = smb + C1_V + j2 * C1_VROW + r2 * 2 + xb0;
#pragma unroll
            for (int mt = 0; mt < 2; mt++) {
                uint32_t af[4];
                af[0] = lds32(a0b + 192 * mt);
                af[1] = lds32(a0b + 192 * mt + 96);
                af[2] = lds32(a2b + 192 * mt);
                af[3] = lds32(a2b + 192 * mt + 96);
#pragma unroll
                for (int nt = 0; nt < 8; nt++) mma_f16(acc[mt][nt], af, &bh[2 * nt]);
            }
        }
    }

    // epilogue: pixel p = bt*16384 + (yp+srow)*128 + x
    size_t pbase = (size_t)bt * 16384 + (size_t)(yp + srow) * 128;
    int xrow = (wid & 3) * 32 + (lane >> 2);
    int cbase = 2 * (lane & 3);
#pragma unroll
    for (int mt = 0; mt < 2; mt++) {
#pragma unroll
        for (int nt = 0; nt < 8; nt++) {
            int col = cbase + nt * 8;
            float b0 = s_bias[col], b1 = s_bias[col + 1];
            size_t r0 = (pbase + xrow + mt * 16) * 64 + col;
            size_t r1 = (pbase + xrow + mt * 16 + 8) * 64 + col;
            float a0 = fmaxf(acc[mt][nt][0] + b0, 0.f);
            float a1 = fmaxf(acc[mt][nt][1] + b1, 0.f);
            float a2 = fmaxf(acc[mt][nt][2] + b0, 0.f);
            float a3 = fmaxf(acc[mt][nt][3] + b1, 0.f);
            *reinterpret_cast<uint32_t*>(g_f1 + r0) = packh2(a0, a1);
            *reinterpret_cast<uint32_t*>(g_f1 + r1) = packh2(a2, a3);
        }
    }
}

// ---------------------------------------------------------------------------
// Implicit-GEMM 3x3 s2 conv, fp16 single-pass, 3-stage cp.async pipeline.
// Block tile 128 x 128, K chunk 32, 8 warps (2M x 4N).
// ---------------------------------------------------------------------------
template <int CIN, int COUT, int HIN, int WIN, int HOUT, int WOUT>
__global__ void __launch_bounds__(256, 2) conv_mma_kernel(
    const __half* __restrict__ in,
    const __half* __restrict__ wth,
    const float* __restrict__ bias,
    __half* __restrict__ outh)
{
    extern __shared__ char sm[];
    __shared__ float s_bias[128];

    const int KTOT = 9 * CIN;
    const int CPP  = CIN / 32;
    const int NT   = 9 * CPP;

    int tid  = threadIdx.x;
    int lane = tid & 31;
    int wid  = tid >> 5;
    int wm   = wid & 1;
    int wn   = wid >> 1;
    int cobase = blockIdx.y * 128;

    if (tid < 128) s_bias[tid] = bias[cobase + tid];

    int fr = tid >> 1;
    int fo = (tid & 1) * 16;
    int p  = blockIdx.x * 128 + fr;
    int fx = p % WOUT;
    int fy = (p / WOUT) % HOUT;
    int fbt = p / (WOUT * HOUT);
    const __half* bsh = wth + (size_t)(cobase + fr) * KTOT + fo;

    uint32_t smb = smem_u32(sm);

    int aoff = ((((lane >> 3) & 1) * 8 + (lane & 7)) * RS) + ((lane >> 4) * 8) * 2;
    int boff = (((lane >> 4) * 8 + (lane & 7)) * RS) + (((lane >> 3) & 1) * 8) * 2;

    float acc[4][4][4];
#pragma unroll
    for (int i = 0; i < 4; i++)
#pragma unroll
        for (int j = 0; j < 4; j++)
#pragma unroll
            for (int k = 0; k < 4; k++) acc[i][j][k] = 0.0f;

    auto FILL = [&](int s, int kt) {
        int pos = kt / CPP, ci0 = (kt - pos * CPP) * 32;
        int dy = pos / 3, dx = pos - dy * 3;
        int iy = 2 * fy + dy, ix = 2 * fx + dx;
        bool valid = (iy < HIN) && (ix < WIN);
        uint32_t vs = valid ? 16u : 0u;
        size_t asrc = valid
            ? ((((size_t)fbt * HIN + iy) * WIN + ix) * CIN + ci0 + fo) : 0;
        uint32_t d = smb + s * STG2 + fr * RS + fo * 2;
        cp16(d,             in + asrc,         vs);
        cp16(d + 16,        in + asrc + 8,     vs);
        cp16(d + MATB,      bsh + kt * 32,     16u);
        cp16(d + MATB + 16, bsh + kt * 32 + 8, 16u);
    };

    auto COMPUTE = [&](int s) {
        uint32_t ab = smb + s * STG2;
#pragma unroll
        for (int ks = 0; ks < 2; ks++) {
            uint32_t bh[8];
#pragma unroll
            for (int q = 0; q < 2; q++) {
                uint32_t ro = boff + (wn * 32 + q * 16) * RS + ks * 32;
                ldmx4(&bh[4 * q], ab + MATB + ro);
            }
#pragma unroll
            for (int mt = 0; mt < 4; mt++) {
                uint32_t af[4];
                ldmx4(af, ab + aoff + (wm * 64 + mt * 16) * RS + ks * 32);
#pragma unroll
                for (int nt = 0; nt < 4; nt++) mma_f16(acc[mt][nt], af, &bh[2 * nt]);
            }
        }
    };

    FILL(0, 0); CP_COMMIT();
    FILL(1, 1); CP_COMMIT();
#pragma unroll 1
    for (int kt = 0; kt < NT; kt++) {
        if (kt + 1 < NT) { CP_WAIT1(); } else { CP_WAIT0(); }
        __syncthreads();
        if (kt + 2 < NT) { FILL((kt + 2) % 3, kt + 2); CP_COMMIT(); }
        COMPUTE(kt % 3);
    }

    int mrow = blockIdx.x * 128 + wm * 64 + (lane >> 2);
    int cbase = wn * 32 + 2 * (lane & 3);
#pragma unroll
    for (int mt = 0; mt < 4; mt++) {
#pragma unroll
        for (int nt = 0; nt < 4; nt++) {
            int col = cbase + nt * 8;
            float b0 = s_bias[col], b1 = s_bias[col + 1];
            size_t r0 = (size_t)(mrow + mt * 16) * COUT + cobase + col;
            size_t r1 = (size_t)(mrow + mt * 16 + 8) * COUT + cobase + col;
            float a0 = fmaxf(acc[mt][nt][0] + b0, 0.f);
            float a1 = fmaxf(acc[mt][nt][1] + b1, 0.f);
            float a2 = fmaxf(acc[mt][nt][2] + b0, 0.f);
            float a3 = fmaxf(acc[mt][nt][3] + b1, 0.f);
            *reinterpret_cast<uint32_t*>(outh + r0) = packh2(a0, a1);
            *reinterpret_cast<uint32_t*>(outh + r1) = packh2(a2, a3);
        }
    }
}

// ---------------------------------------------------------------------------
// corr GEMM: D = Q . X^T / 16; fp16 in/out, 3-stage pipeline.
// ---------------------------------------------------------------------------
__global__ void __launch_bounds__(256, 2) corr_mma_kernel()
{
    extern __shared__ char sm[];

    int tid  = threadIdx.x;
    int lane = tid & 31;
    int wid  = tid >> 5;
    int wm   = wid & 1;
    int wn   = wid >> 1;

    int bt  = blockIdx.z;
    int b   = bt / 24;
    int n0  = blockIdx.y * 128;
    int hw0 = blockIdx.x * 128;

    int fr = tid >> 1;
    int fo = (tid & 1) * 16;
    const __half* ah = g_qh + ((size_t)b * 512 + n0 + fr) * 256 + fo;
    const __half* bx = g_f3 + ((size_t)bt * 1024 + hw0 + fr) * 256 + fo;

    uint32_t smb = smem_u32(sm);

    int aoff = ((((lane >> 3) & 1) * 8 + (lane & 7)) * RS) + ((lane >> 4) * 8) * 2;
    int boff = (((lane >> 4) * 8 + (lane & 7)) * RS) + (((lane >> 3) & 1) * 8) * 2;

    float acc[4][4][4];
#pragma unroll
    for (int i = 0; i < 4; i++)
#pragma unroll
        for (int j = 0; j < 4; j++)
#pragma unroll
            for (int k = 0; k < 4; k++) acc[i][j][k] = 0.0f;

    auto FILL = [&](int s, int kt) {
        uint32_t d = smb + s * STG2 + fr * RS + fo * 2;
        cp16(d,             ah + kt * 32,     16u);
        cp16(d + 16,        ah + kt * 32 + 8, 16u);
        cp16(d + MATB,      bx + kt * 32,     16u);
        cp16(d + MATB + 16, bx + kt * 32 + 8, 16u);
    };

    auto COMPUTE = [&](int s) {
        uint32_t ab = smb + s * STG2;
#pragma unroll
        for (int ks = 0; ks < 2; ks++) {
            uint32_t bxr[8];
#pragma unroll
            for (int q = 0; q < 2; q++) {
                uint32_t ro = boff + (wn * 32 + q * 16) * RS + ks * 32;
                ldmx4(&bxr[4 * q], ab + MATB + ro);
            }
#pragma unroll
            for (int mt = 0; mt < 4; mt++) {
                uint32_t af[4];
                ldmx4(af, ab + aoff + (wm * 64 + mt * 16) * RS + ks * 32);
#pragma unroll
                for (int nt = 0; nt < 4; nt++) mma_f16(acc[mt][nt], af, &bxr[2 * nt]);
            }
        }
    };

    FILL(0, 0); CP_COMMIT();
    FILL(1, 1); CP_COMMIT();
#pragma unroll 1
    for (int kt = 0; kt < 8; kt++) {
        if (kt + 1 < 8) { CP_WAIT1(); } else { CP_WAIT0(); }
        __syncthreads();
        if (kt + 2 < 8) { FILL((kt + 2) % 3, kt + 2); CP_COMMIT(); }
        COMPUTE(kt % 3);
    }

    __half* C = g_corrh + (size_t)bt * 512 * 1024;
    int mrow = n0 + wm * 64 + (lane >> 2);
    int cbase = hw0 + wn * 32 + 2 * (lane & 3);
#pragma unroll
    for (int mt = 0; mt < 4; mt++) {
#pragma unroll
        for (int nt = 0; nt < 4; nt++) {
            int col = cbase + nt * 8;
            int r0 = mrow + mt * 16;
            *reinterpret_cast<uint32_t*>(C + (size_t)r0 * 1024 + col) =
                packh2(acc[mt][nt][0] * 0.0625f, acc[mt][nt][1] * 0.0625f);
            *reinterpret_cast<uint32_t*>(C + (size_t)(r0 + 8) * 1024 + col) =
                packh2(acc[mt][nt][2] * 0.0625f, acc[mt][nt][3] * 0.0625f);
        }
    }
}

// ---------------------------------------------------------------------------
// Bilinear sampling from fp16 feat3 -> q fp16
// ---------------------------------------------------------------------------
__global__ void __launch_bounds__(256) sample_kernel(const float* __restrict__ qp)
{
    int bn = blockIdx.x;
    float q0 = qp[bn * 3 + 0];
    float q1 = qp[bn * 3 + 1];
    float q2 = qp[bn * 3 + 2];

    int t = (int)(q0 * 23.0f);
    t = min(max(t, 0), 23);
    float yf = q1 * 31.0f;
    float xf = q2 * 31.0f;
    int y0 = min(max((int)floorf(yf), 0), 31);
    int y1 = min(y0 + 1, 31);
    int x0 = min(max((int)floorf(xf), 0), 31);
    int x1 = min(x0 + 1, 31);
    float wy1 = yf - (float)y0, wy0 = 1.0f - wy1;
    float wx1 = xf - (float)x0, wx0 = 1.0f - wx1;

    int b = bn >> 9;
    const __half* f = g_f3 + (size_t)(b * 24 + t) * 1024 * 256;
    int c = threadIdx.x;
    float f00 = __half2float(f[(size_t)(y0 * 32 + x0) * 256 + c]);
    float f01 = __half2float(f[(size_t)(y0 * 32 + x1) * 256 + c]);
    float f10 = __half2float(f[(size_t)(y1 * 32 + x0) * 256 + c]);
    float f11 = __half2float(f[(size_t)(y1 * 32 + x1) * 256 + c]);
    float f0 = f00 * wx0 + f01 * wx1;
    float f1 = f10 * wx0 + f11 * wx1;
    float v = f0 * wy0 + f1 * wy1;
    g_qh[(size_t)bn * 256 + c] = __float2half(v);
}

// ---------------------------------------------------------------------------
// Fused softmax(corr*10) expectation + occlusion (fp16 corr input).
// ---------------------------------------------------------------------------
__global__ void __launch_bounds__(256) finalize_kernel(float* __restrict__ out)
{
    int gwarp = (blockIdx.x * 256 + threadIdx.x) >> 5;
    int lane  = threadIdx.x & 31;

    const __half* c = g_corrh + (size_t)gwarp * 1024;
    float v[32];
    float m = -1e30f;
#pragma unroll
    for (int i = 0; i < 4; i++) {
        uint4 t4 = *reinterpret_cast<const uint4*>(c + i * 256 + lane * 8);
        const uint32_t w[4] = {t4.x, t4.y, t4.z, t4.w};
#pragma unroll
        for (int q = 0; q < 4; q++) {
            __half2 h2 = *reinterpret_cast<const __half2*>(&w[q]);
            float f0 = __half2float(h2.x);
            float f1 = __half2float(h2.y);
            v[i * 8 + 2 * q + 0] = f0;
            v[i * 8 + 2 * q + 1] = f1;
            m = fmaxf(m, fmaxf(f0, f1));
        }
    }
#pragma unroll
    for (int o = 16; o > 0; o >>= 1)
        m = fmaxf(m, __shfl_xor_sync(0xffffffffu, m, o));

    float s = 0.0f, sx = 0.0f, sy = 0.0f;
#pragma unroll
    for (int i = 0; i < 4; i++) {
#pragma unroll
        for (int j = 0; j < 8; j++) {
            int idx = i * 256 + lane * 8 + j;
            float e = __expf(10.0f * (v[i * 8 + j] - m));
            s  += e;
            sx += e * (float)(idx & 31);
            sy += e * (float)(idx >> 5);
        }
    }
#pragma unroll
    for (int o = 16; o > 0; o >>= 1) {
        s  += __shfl_xor_sync(0xffffffffu, s, o);
        sx += __shfl_xor_sync(0xffffffffu, sx, o);
        sy += __shfl_xor_sync(0xffffffffu, sy, o);
    }

    if (lane == 0) {
        int bt = gwarp >> 9;
        int n  = gwarp & 511;
        int b  = bt / 24;
        int t  = bt - b * 24;
        int o  = (b * 512 + n) * 24 + t;
        float inv = 8.0f / s;
        out[2 * o + 0] = sx * inv;
        out[2 * o + 1] = sy * inv;
        out[2 * 24576 + o] = 1.0f / (1.0f + __expf(m));
    }
}

// ---------------------------------------------------------------------------
// Launch
// ---------------------------------------------------------------------------
extern "C" void kernel_launch(void* const* d_in, const int* in_sizes, int n_in,
                              void* d_out, int out_size)
{
    const float* video = (const float*)d_in[0];
    const float* qp    = (const float*)d_in[1];
    const float* w1    = (const float*)d_in[2];
    const float* b1    = (const float*)d_in[3];
    const float* w2    = (const float*)d_in[4];
    const float* b2    = (const float*)d_in[5];
    const float* w3    = (const float*)d_in[6];
    const float* b3    = (const float*)d_in[7];

    __half *f1, *f2, *f3, *wt2h, *wt3h;
    cudaGetSymbolAddress((void**)&f1, g_f1);
    cudaGetSymbolAddress((void**)&f2, g_f2);
    cudaGetSymbolAddress((void**)&f3, g_f3);
    cudaGetSymbolAddress((void**)&wt2h, g_w2h);
    cudaGetSymbolAddress((void**)&wt3h, g_w3h);

    cudaFuncSetAttribute((const void*)conv1_fused_kernel,
                         cudaFuncAttributeMaxDynamicSharedMemorySize, DSMEM_C1);
    cudaFuncSetAttribute(
        (const void*)conv_mma_kernel<64, 128, 128, 128, 64, 64>,
        cudaFuncAttributeMaxDynamicSharedMemorySize, DSMEM_CONV);
    cudaFuncSetAttribute(
        (const void*)conv_mma_kernel<128, 256, 64, 64, 32, 32>,
        cudaFuncAttributeMaxDynamicSharedMemorySize, DSMEM_CONV);
    cudaFuncSetAttribute((const void*)corr_mma_kernel,
                         cudaFuncAttributeMaxDynamicSharedMemorySize, DSMEM_CONV);

    // weight prep (tiny)
    prep_w1_kernel<<<40, 256>>>(w1);
    transpose_w<<<(576 * 128 + 255) / 256, 256>>>(w2, wt2h, 576, 128);
    transpose_w<<<(1152 * 256 + 255) / 256, 256>>>(w3, wt3h, 1152, 256);

    // conv1 fused v6: one block per (bt, row-pair)
    conv1_fused_kernel<<<48 * 64, 256, DSMEM_C1>>>(video, b1);

    // conv2: 196608 px / 128 = 1536 tiles
    conv_mma_kernel<64, 128, 128, 128, 64, 64>
        <<<dim3(1536, 1, 1), 256, DSMEM_CONV>>>(f1, wt2h, b2, f2);

    // conv3: 384 tiles x 2 N-chunks
    conv_mma_kernel<128, 256, 64, 64, 32, 32>
        <<<dim3(384, 2, 1), 256, DSMEM_CONV>>>(f2, wt3h, b3, f3);

    // sampling -> q fp16
    sample_kernel<<<1024, 256>>>(qp);

    // corr GEMM -> fp16 corr
    corr_mma_kernel<<<dim3(8, 4, 48), 256, DSMEM_CONV>>>();

    // softmax + expectation + occlusion
    finalize_kernel<<<3072, 256>>>((float*)d_out);
}

// round 17
// speedup vs baseline: 1.0203x; 1.0002x over previous
#include <cuda_runtime.h>
#include <cuda_fp16.h>
#include <math.h>
#include <stdint.h>

// ---------------------------------------------------------------------------
// B=2, T=24, H=256, W=256, N=512, HIDDEN=256
// conv1: fused, direct-LDS A, dense K=160, 2 rows/block, 8Mx1N warps
// conv2: 3x3x64->128 s2  implicit GEMM mma fp16, 3-stage pipeline
// conv3: 3x3x128->256 s2 implicit GEMM mma fp16, 3-stage pipeline
// corr : [48] 512x1024x256 GEMM mma fp16 -> corr fp16
// finalize: softmax via FFMA-pipe poly exp2 (no MUFU)
// ---------------------------------------------------------------------------

__device__ __half g_f1[2 * 24 * 128 * 128 * 64];          // 100 MB
__device__ __half g_f2[2 * 24 * 64 * 64 * 128];           //  50 MB
__device__ __half g_f3[2 * 24 * 32 * 32 * 256];           //  25 MB
__device__ __half g_qh[2 * 512 * 256];
__device__ __half g_corrh[2 * 24 * 512 * 1024];           //  50 MB (fp16 corr)
__device__ __half g_w1h[64 * 160];                        // conv1 W [cout][160]
__device__ __half g_w2h[128 * 576];
__device__ __half g_w3h[256 * 1152];

// ---------------------------------------------------------------------------
// helpers
// ---------------------------------------------------------------------------
__device__ __forceinline__ uint32_t smem_u32(const void* p) {
    uint32_t a;
    asm("{ .reg .u64 t; cvta.to.shared.u64 t, %1; cvt.u32.u64 %0, t; }"
        : "=r"(a) : "l"(p));
    return a;
}

__device__ __forceinline__ void cp16(uint32_t dst, const void* gsrc, uint32_t ss) {
    asm volatile(
        "{ .reg .u64 g; cvta.to.global.u64 g, %1;"
        "  cp.async.ca.shared.global [%0], [g], 16, %2; }"
        :: "r"(dst), "l"(gsrc), "r"(ss) : "memory");
}
#define CP_COMMIT() asm volatile("cp.async.commit_group;" ::: "memory")
#define CP_WAIT1()  asm volatile("cp.async.wait_group 1;" ::: "memory")
#define CP_WAIT0()  asm volatile("cp.async.wait_group 0;" ::: "memory")

__device__ __forceinline__ void ldmx4(uint32_t* r, uint32_t addr) {
    asm volatile(
        "ldmatrix.sync.aligned.m8n8.x4.shared.b16 {%0,%1,%2,%3}, [%4];"
        : "=r"(r[0]), "=r"(r[1]), "=r"(r[2]), "=r"(r[3]) : "r"(addr));
}

__device__ __forceinline__ uint32_t lds32(uint32_t addr) {
    uint32_t v;
    asm volatile("ld.shared.b32 %0, [%1];" : "=r"(v) : "r"(addr));
    return v;
}

__device__ __forceinline__ void mma_f16(float* d, const uint32_t* a,
                                        const uint32_t* b) {
    asm volatile(
        "mma.sync.aligned.m16n8k16.row.col.f32.f16.f16.f32 "
        "{%0,%1,%2,%3}, {%4,%5,%6,%7}, {%8,%9}, {%0,%1,%2,%3};"
        : "+f"(d[0]), "+f"(d[1]), "+f"(d[2]), "+f"(d[3])
        : "r"(a[0]), "r"(a[1]), "r"(a[2]), "r"(a[3]), "r"(b[0]), "r"(b[1]));
}

__device__ __forceinline__ uint32_t packh2(float a, float b) {
    __half2 t = __floats2half2_rn(a, b);
    return *reinterpret_cast<uint32_t*>(&t);
}

// e^(10*d) for d <= 0, FFMA-pipe only (poly 2^f, deg 5, rel err ~1e-7)
__device__ __forceinline__ float fast_exp10(float d) {
    float y = fmaxf(d * 14.4269504089f, -125.0f);   // 10*log2(e)
    float yi = floorf(y);
    float f = y - yi;
    float p = 1.3358911e-3f;
    p = fmaf(p, f, 9.6180287e-3f);
    p = fmaf(p, f, 5.5503333e-2f);
    p = fmaf(p, f, 2.4022652e-1f);
    p = fmaf(p, f, 6.9314718e-1f);
    p = fmaf(p, f, 1.0f);
    float sc = __int_as_float(((int)yi + 127) << 23);
    return p * sc;
}

// smem tile: rows x 32 fp16, row stride 80 B (16B pad, conflict-free ldmatrix)
#define RS    80
#define MATB  (128 * RS)            // 10240 B (128-row tile)
#define STG2  (2 * MATB)            // A | B (single-pass)
#define DSMEM_CONV (3 * STG2)       // 61440 B, 3-stage pipeline

// conv1 (2 rows/block): B (5 chunks x 64 rows x RS) + V (10 rows)
#define C1_B    0
#define C1_V    (5 * 64 * RS)             // 25600
#define C1_VROW 1600
#define DSMEM_C1 (C1_V + 10 * C1_VROW)    // 41600

// ---------------------------------------------------------------------------
// merged weight prep (one launch):
//  [0, 10240)            : conv1 dense-K  (k = dy*22 + r, zero pads)
//  [10240, 84 * 1024)    : w2 transpose   (K=576, C=128)
//  [84*1024, 372*1024+..): w3 transpose   (K=1152, C=256)
// ---------------------------------------------------------------------------
#define PREP_W1 (64 * 160)
#define PREP_W2 (576 * 128)
#define PREP_W3 (1152 * 256)
__global__ void __launch_bounds__(256) prep_all_kernel(
    const float* __restrict__ w1,
    const float* __restrict__ w2,
    const float* __restrict__ w3)
{
    int i = blockIdx.x * 256 + threadIdx.x;
    if (i < PREP_W1) {
        int c = i / 160, kk = i - c * 160;
        int dy = kk / 22, r = kk - dy * 22;
        float v = (dy < 7 && r < 21) ? w1[(dy * 21 + r) * 64 + c] : 0.f;
        g_w1h[i] = __float2half(v);
        return;
    }
    i -= PREP_W1;
    if (i < PREP_W2) {
        int k = i / 128, c = i - k * 128;
        g_w2h[(size_t)c * 576 + k] = __float2half(w2[i]);
        return;
    }
    i -= PREP_W2;
    if (i < PREP_W3) {
        int k = i / 256, c = i - k * 256;
        g_w3h[(size_t)c * 1152 + k] = __float2half(w3[i]);
    }
}

// ---------------------------------------------------------------------------
// conv1 fused: one block = TWO output rows (bt, yp..yp+1) = 256 px (M).
// 8 warps = 8M x 1N. A per-lane LDS.32 from staged video rows. K=160.
// ---------------------------------------------------------------------------
__global__ void __launch_bounds__(256, 2) conv1_fused_kernel(
    const float* __restrict__ video,
    const float* __restrict__ bias)
{
    extern __shared__ char sm[];
    __shared__ float s_bias[64];

    int tid  = threadIdx.x;
    int lane = tid & 31;
    int wid  = tid >> 5;

    int yp = (blockIdx.x & 63) * 2;
    int bt = blockIdx.x >> 6;

    if (tid < 64) s_bias[tid] = bias[tid];

    uint32_t smb = smem_u32(sm);

    // B preload: 5 chunks x 64 rows x 4 segs = 1280 cp16
    for (int u = tid; u < 1280; u += 256) {
        int seg = u & 3;
        int cc  = (u >> 2) % 5;
        int r   = u / 20;
        const __half* s = g_w1h + r * 160 + cc * 32 + seg * 8;
        uint32_t d = smb + C1_B + (cc * 64 + r) * RS + seg * 16;
        cp16(d, s, 16u);
    }
    CP_COMMIT();

    // zero video smem: 10 rows (9 video + zero row 9)
    uint32_t* vz = reinterpret_cast<uint32_t*>(sm + C1_V);
    for (int u = tid; u < 10 * C1_VROW / 4; u += 256) vz[u] = 0u;
    __syncthreads();

    // video rows j=0..8: iy = 2*yp + j - 2
    const float inv255 = 1.0f / 255.0f;
    for (int u = tid; u < 9 * 384; u += 256) {
        int j = u / 384;
        int m = u - j * 384;
        int iy = 2 * yp + j - 2;
        if ((unsigned)iy < 256u) {
            const float2 v2 = *reinterpret_cast<const float2*>(
                video + ((size_t)(bt * 256 + iy) * 256) * 3 + 2 * m);
            uint32_t pk = packh2(v2.x * inv255, v2.y * inv255);
            *reinterpret_cast<uint32_t*>(sm + C1_V + j * C1_VROW + 12 + 4 * m) = pk;
        }
    }
    CP_WAIT0();
    __syncthreads();

    int srow = wid >> 2;
    uint32_t xb0 = 12u * ((wid & 3) * 32 + (lane >> 2));
    int klane = 2 * (lane & 3);

    int boff = (((lane >> 4) * 8 + (lane & 7)) * RS) + (((lane >> 3) & 1) * 8) * 2;

    float acc[2][8][4];
#pragma unroll
    for (int i = 0; i < 2; i++)
#pragma unroll
        for (int j = 0; j < 8; j++)
#pragma unroll
            for (int k = 0; k < 4; k++) acc[i][j][k] = 0.0f;

#pragma unroll
    for (int cc = 0; cc < 5; cc++) {
        uint32_t bb = smb + C1_B + cc * (64 * RS);
#pragma unroll
        for (int ks = 0; ks < 2; ks++) {
            uint32_t bh[16];
#pragma unroll
            for (int q = 0; q < 4; q++) {
                uint32_t ro = boff + (q * 16) * RS + ks * 32;
                ldmx4(&bh[4 * q], bb + ro);
            }
            int k0  = cc * 32 + ks * 16 + klane;
            int dy0 = k0 / 22, r0 = k0 - 22 * dy0;
            int k2  = k0 + 8;
            int dy2 = k2 / 22, r2 = k2 - 22 * dy2;
            int j0 = (dy0 < 7) ? (dy0 + 2 * srow) : 9;
            int j2 = (dy2 < 7) ? (dy2 + 2 * srow) : 9;
            uint32_t a0b = smb + C1_V + j0 * C1_VROW + r0 * 2 + xb0;
            uint32_t a2b = smb + C1_V + j2 * C1_VROW + r2 * 2 + xb0;
#pragma unroll
            for (int mt = 0; mt < 2; mt++) {
                uint32_t af[4];
                af[0] = lds32(a0b + 192 * mt);
                af[1] = lds32(a0b + 192 * mt + 96);
                af[2] = lds32(a2b + 192 * mt);
                af[3] = lds32(a2b + 192 * mt + 96);
#pragma unroll
                for (int nt = 0; nt < 8; nt++) mma_f16(acc[mt][nt], af, &bh[2 * nt]);
            }
        }
    }

    size_t pbase = (size_t)bt * 16384 + (size_t)(yp + srow) * 128;
    int xrow = (wid & 3) * 32 + (lane >> 2);
    int cbase = 2 * (lane & 3);
#pragma unroll
    for (int mt = 0; mt < 2; mt++) {
#pragma unroll
        for (int nt = 0; nt < 8; nt++) {
            int col = cbase + nt * 8;
            float b0 = s_bias[col], b1 = s_bias[col + 1];
            size_t r0 = (pbase + xrow + mt * 16) * 64 + col;
            size_t r1 = (pbase + xrow + mt * 16 + 8) * 64 + col;
            float a0 = fmaxf(acc[mt][nt][0] + b0, 0.f);
            float a1 = fmaxf(acc[mt][nt][1] + b1, 0.f);
            float a2 = fmaxf(acc[mt][nt][2] + b0, 0.f);
            float a3 = fmaxf(acc[mt][nt][3] + b1, 0.f);
            *reinterpret_cast<uint32_t*>(g_f1 + r0) = packh2(a0, a1);
            *reinterpret_cast<uint32_t*>(g_f1 + r1) = packh2(a2, a3);
        }
    }
}

// ---------------------------------------------------------------------------
// Implicit-GEMM 3x3 s2 conv, fp16 single-pass, 3-stage cp.async pipeline.
// ---------------------------------------------------------------------------
template <int CIN, int COUT, int HIN, int WIN, int HOUT, int WOUT>
__global__ void __launch_bounds__(256, 2) conv_mma_kernel(
    const __half* __restrict__ in,
    const __half* __restrict__ wth,
    const float* __restrict__ bias,
    __half* __restrict__ outh)
{
    extern __shared__ char sm[];
    __shared__ float s_bias[128];

    const int KTOT = 9 * CIN;
    const int CPP  = CIN / 32;
    const int NT   = 9 * CPP;

    int tid  = threadIdx.x;
    int lane = tid & 31;
    int wid  = tid >> 5;
    int wm   = wid & 1;
    int wn   = wid >> 1;
    int cobase = blockIdx.y * 128;

    if (tid < 128) s_bias[tid] = bias[cobase + tid];

    int fr = tid >> 1;
    int fo = (tid & 1) * 16;
    int p  = blockIdx.x * 128 + fr;
    int fx = p % WOUT;
    int fy = (p / WOUT) % HOUT;
    int fbt = p / (WOUT * HOUT);
    const __half* bsh = wth + (size_t)(cobase + fr) * KTOT + fo;

    uint32_t smb = smem_u32(sm);

    int aoff = ((((lane >> 3) & 1) * 8 + (lane & 7)) * RS) + ((lane >> 4) * 8) * 2;
    int boff = (((lane >> 4) * 8 + (lane & 7)) * RS) + (((lane >> 3) & 1) * 8) * 2;

    float acc[4][4][4];
#pragma unroll
    for (int i = 0; i < 4; i++)
#pragma unroll
        for (int j = 0; j < 4; j++)
#pragma unroll
            for (int k = 0; k < 4; k++) acc[i][j][k] = 0.0f;

    auto FILL = [&](int s, int kt) {
        int pos = kt / CPP, ci0 = (kt - pos * CPP) * 32;
        int dy = pos / 3, dx = pos - dy * 3;
        int iy = 2 * fy + dy, ix = 2 * fx + dx;
        bool valid = (iy < HIN) && (ix < WIN);
        uint32_t vs = valid ? 16u : 0u;
        size_t asrc = valid
            ? ((((size_t)fbt * HIN + iy) * WIN + ix) * CIN + ci0 + fo) : 0;
        uint32_t d = smb + s * STG2 + fr * RS + fo * 2;
        cp16(d,             in + asrc,         vs);
        cp16(d + 16,        in + asrc + 8,     vs);
        cp16(d + MATB,      bsh + kt * 32,     16u);
        cp16(d + MATB + 16, bsh + kt * 32 + 8, 16u);
    };

    auto COMPUTE = [&](int s) {
        uint32_t ab = smb + s * STG2;
#pragma unroll
        for (int ks = 0; ks < 2; ks++) {
            uint32_t bh[8];
#pragma unroll
            for (int q = 0; q < 2; q++) {
                uint32_t ro = boff + (wn * 32 + q * 16) * RS + ks * 32;
                ldmx4(&bh[4 * q], ab + MATB + ro);
            }
#pragma unroll
            for (int mt = 0; mt < 4; mt++) {
                uint32_t af[4];
                ldmx4(af, ab + aoff + (wm * 64 + mt * 16) * RS + ks * 32);
#pragma unroll
                for (int nt = 0; nt < 4; nt++) mma_f16(acc[mt][nt], af, &bh[2 * nt]);
            }
        }
    };

    FILL(0, 0); CP_COMMIT();
    FILL(1, 1); CP_COMMIT();
#pragma unroll 1
    for (int kt = 0; kt < NT; kt++) {
        if (kt + 1 < NT) { CP_WAIT1(); } else { CP_WAIT0(); }
        __syncthreads();
        if (kt + 2 < NT) { FILL((kt + 2) % 3, kt + 2); CP_COMMIT(); }
        COMPUTE(kt % 3);
    }

    int mrow = blockIdx.x * 128 + wm * 64 + (lane >> 2);
    int cbase = wn * 32 + 2 * (lane & 3);
#pragma unroll
    for (int mt = 0; mt < 4; mt++) {
#pragma unroll
        for (int nt = 0; nt < 4; nt++) {
            int col = cbase + nt * 8;
            float b0 = s_bias[col], b1 = s_bias[col + 1];
            size_t r0 = (size_t)(mrow + mt * 16) * COUT + cobase + col;
            size_t r1 = (size_t)(mrow + mt * 16 + 8) * COUT + cobase + col;
            float a0 = fmaxf(acc[mt][nt][0] + b0, 0.f);
            float a1 = fmaxf(acc[mt][nt][1] + b1, 0.f);
            float a2 = fmaxf(acc[mt][nt][2] + b0, 0.f);
            float a3 = fmaxf(acc[mt][nt][3] + b1, 0.f);
            *reinterpret_cast<uint32_t*>(outh + r0) = packh2(a0, a1);
            *reinterpret_cast<uint32_t*>(outh + r1) = packh2(a2, a3);
        }
    }
}

// ---------------------------------------------------------------------------
// corr GEMM: D = Q . X^T / 16; fp16 in/out, 3-stage pipeline.
// ---------------------------------------------------------------------------
__global__ void __launch_bounds__(256, 2) corr_mma_kernel()
{
    extern __shared__ char sm[];

    int tid  = threadIdx.x;
    int lane = tid & 31;
    int wid  = tid >> 5;
    int wm   = wid & 1;
    int wn   = wid >> 1;

    int bt  = blockIdx.z;
    int b   = bt / 24;
    int n0  = blockIdx.y * 128;
    int hw0 = blockIdx.x * 128;

    int fr = tid >> 1;
    int fo = (tid & 1) * 16;
    const __half* ah = g_qh + ((size_t)b * 512 + n0 + fr) * 256 + fo;
    const __half* bx = g_f3 + ((size_t)bt * 1024 + hw0 + fr) * 256 + fo;

    uint32_t smb = smem_u32(sm);

    int aoff = ((((lane >> 3) & 1) * 8 + (lane & 7)) * RS) + ((lane >> 4) * 8) * 2;
    int boff = (((lane >> 4) * 8 + (lane & 7)) * RS) + (((lane >> 3) & 1) * 8) * 2;

    float acc[4][4][4];
#pragma unroll
    for (int i = 0; i < 4; i++)
#pragma unroll
        for (int j = 0; j < 4; j++)
#pragma unroll
            for (int k = 0; k < 4; k++) acc[i][j][k] = 0.0f;

    auto FILL = [&](int s, int kt) {
        uint32_t d = smb + s * STG2 + fr * RS + fo * 2;
        cp16(d,             ah + kt * 32,     16u);
        cp16(d + 16,        ah + kt * 32 + 8, 16u);
        cp16(d + MATB,      bx + kt * 32,     16u);
        cp16(d + MATB + 16, bx + kt * 32 + 8, 16u);
    };

    auto COMPUTE = [&](int s) {
        uint32_t ab = smb + s * STG2;
#pragma unroll
        for (int ks = 0; ks < 2; ks++) {
            uint32_t bxr[8];
#pragma unroll
            for (int q = 0; q < 2; q++) {
                uint32_t ro = boff + (wn * 32 + q * 16) * RS + ks * 32;
                ldmx4(&bxr[4 * q], ab + MATB + ro);
            }
#pragma unroll
            for (int mt = 0; mt < 4; mt++) {
                uint32_t af[4];
                ldmx4(af, ab + aoff + (wm * 64 + mt * 16) * RS + ks * 32);
#pragma unroll
                for (int nt = 0; nt < 4; nt++) mma_f16(acc[mt][nt], af, &bxr[2 * nt]);
            }
        }
    };

    FILL(0, 0); CP_COMMIT();
    FILL(1, 1); CP_COMMIT();
#pragma unroll 1
    for (int kt = 0; kt < 8; kt++) {
        if (kt + 1 < 8) { CP_WAIT1(); } else { CP_WAIT0(); }
        __syncthreads();
        if (kt + 2 < 8) { FILL((kt + 2) % 3, kt + 2); CP_COMMIT(); }
        COMPUTE(kt % 3);
    }

    __half* C = g_corrh + (size_t)bt * 512 * 1024;
    int mrow = n0 + wm * 64 + (lane >> 2);
    int cbase = hw0 + wn * 32 + 2 * (lane & 3);
#pragma unroll
    for (int mt = 0; mt < 4; mt++) {
#pragma unroll
        for (int nt = 0; nt < 4; nt++) {
            int col = cbase + nt * 8;
            int r0 = mrow + mt * 16;
            *reinterpret_cast<uint32_t*>(C + (size_t)r0 * 1024 + col) =
                packh2(acc[mt][nt][0] * 0.0625f, acc[mt][nt][1] * 0.0625f);
            *reinterpret_cast<uint32_t*>(C + (size_t)(r0 + 8) * 1024 + col) =
                packh2(acc[mt][nt][2] * 0.0625f, acc[mt][nt][3] * 0.0625f);
        }
    }
}

// ---------------------------------------------------------------------------
// Bilinear sampling from fp16 feat3 -> q fp16
// ---------------------------------------------------------------------------
__global__ void __launch_bounds__(256) sample_kernel(const float* __restrict__ qp)
{
    int bn = blockIdx.x;
    float q0 = qp[bn * 3 + 0];
    float q1 = qp[bn * 3 + 1];
    float q2 = qp[bn * 3 + 2];

    int t = (int)(q0 * 23.0f);
    t = min(max(t, 0), 23);
    float yf = q1 * 31.0f;
    float xf = q2 * 31.0f;
    int y0 = min(max((int)floorf(yf), 0), 31);
    int y1 = min(y0 + 1, 31);
    int x0 = min(max((int)floorf(xf), 0), 31);
    int x1 = min(x0 + 1, 31);
    float wy1 = yf - (float)y0, wy0 = 1.0f - wy1;
    float wx1 = xf - (float)x0, wx0 = 1.0f - wx1;

    int b = bn >> 9;
    const __half* f = g_f3 + (size_t)(b * 24 + t) * 1024 * 256;
    int c = threadIdx.x;
    float f00 = __half2float(f[(size_t)(y0 * 32 + x0) * 256 + c]);
    float f01 = __half2float(f[(size_t)(y0 * 32 + x1) * 256 + c]);
    float f10 = __half2float(f[(size_t)(y1 * 32 + x0) * 256 + c]);
    float f11 = __half2float(f[(size_t)(y1 * 32 + x1) * 256 + c]);
    float f0 = f00 * wx0 + f01 * wx1;
    float f1 = f10 * wx0 + f11 * wx1;
    float v = f0 * wy0 + f1 * wy1;
    g_qh[(size_t)bn * 256 + c] = __float2half(v);
}

// ---------------------------------------------------------------------------
// Fused softmax(corr*10) expectation + occlusion (fp16 corr input).
// exp on the FFMA pipe (poly exp2); no MUFU in the hot loop.
// ---------------------------------------------------------------------------
__global__ void __launch_bounds__(256) finalize_kernel(float* __restrict__ out)
{
    int gwarp = (blockIdx.x * 256 + threadIdx.x) >> 5;
    int lane  = threadIdx.x & 31;

    const __half* c = g_corrh + (size_t)gwarp * 1024;
    float v[32];
    float m = -1e30f;
#pragma unroll
    for (int i = 0; i < 4; i++) {
        uint4 t4 = *reinterpret_cast<const uint4*>(c + i * 256 + lane * 8);
        const uint32_t w[4] = {t4.x, t4.y, t4.z, t4.w};
#pragma unroll
        for (int q = 0; q < 4; q++) {
            __half2 h2 = *reinterpret_cast<const __half2*>(&w[q]);
            float f0 = __half2float(h2.x);
            float f1 = __half2float(h2.y);
            v[i * 8 + 2 * q + 0] = f0;
            v[i * 8 + 2 * q + 1] = f1;
            m = fmaxf(m, fmaxf(f0, f1));
        }
    }
#pragma unroll
    for (int o = 16; o > 0; o >>= 1)
        m = fmaxf(m, __shfl_xor_sync(0xffffffffu, m, o));

    float s = 0.0f, sx = 0.0f, sy = 0.0f;
#pragma unroll
    for (int i = 0; i < 4; i++) {
#pragma unroll
        for (int j = 0; j < 8; j++) {
            int idx = i * 256 + lane * 8 + j;
            float e = fast_exp10(v[i * 8 + j] - m);
            s  += e;
            sx += e * (float)(idx & 31);
            sy += e * (float)(idx >> 5);
        }
    }
#pragma unroll
    for (int o = 16; o > 0; o >>= 1) {
        s  += __shfl_xor_sync(0xffffffffu, s, o);
        sx += __shfl_xor_sync(0xffffffffu, sx, o);
        sy += __shfl_xor_sync(0xffffffffu, sy, o);
    }

    if (lane == 0) {
        int bt = gwarp >> 9;
        int n  = gwarp & 511;
        int b  = bt / 24;
        int t  = bt - b * 24;
        int o  = (b * 512 + n) * 24 + t;
        float inv = 8.0f / s;
        out[2 * o + 0] = sx * inv;
        out[2 * o + 1] = sy * inv;
        out[2 * 24576 + o] = 1.0f / (1.0f + __expf(m));
    }
}

// ---------------------------------------------------------------------------
// Launch
// ---------------------------------------------------------------------------
extern "C" void kernel_launch(void* const* d_in, const int* in_sizes, int n_in,
                              void* d_out, int out_size)
{
    const float* video = (const float*)d_in[0];
    const float* qp    = (const float*)d_in[1];
    const float* w1    = (const float*)d_in[2];
    const float* b1    = (const float*)d_in[3];
    const float* w2    = (const float*)d_in[4];
    const float* b2    = (const float*)d_in[5];
    const float* w3    = (const float*)d_in[6];
    const float* b3    = (const float*)d_in[7];

    __half *f1, *f2, *f3, *wt2h, *wt3h;
    cudaGetSymbolAddress((void**)&f1, g_f1);
    cudaGetSymbolAddress((void**)&f2, g_f2);
    cudaGetSymbolAddress((void**)&f3, g_f3);
    cudaGetSymbolAddress((void**)&wt2h, g_w2h);
    cudaGetSymbolAddress((void**)&wt3h, g_w3h);

    cudaFuncSetAttribute((const void*)conv1_fused_kernel,
                         cudaFuncAttributeMaxDynamicSharedMemorySize, DSMEM_C1);
    cudaFuncSetAttribute(
        (const void*)conv_mma_kernel<64, 128, 128, 128, 64, 64>,
        cudaFuncAttributeMaxDynamicSharedMemorySize, DSMEM_CONV);
    cudaFuncSetAttribute(
        (const void*)conv_mma_kernel<128, 256, 64, 64, 32, 32>,
        cudaFuncAttributeMaxDynamicSharedMemorySize, DSMEM_CONV);
    cudaFuncSetAttribute((const void*)corr_mma_kernel,
                         cudaFuncAttributeMaxDynamicSharedMemorySize, DSMEM_CONV);

    // merged weight prep (one launch)
    const int PREP_TOT = PREP_W1 + PREP_W2 + PREP_W3;
    prep_all_kernel<<<(PREP_TOT + 255) / 256, 256>>>(w1, w2, w3);

    // conv1 fused: one block per (bt, row-pair)
    conv1_fused_kernel<<<48 * 64, 256, DSMEM_C1>>>(video, b1);

    // conv2: 196608 px / 128 = 1536 tiles
    conv_mma_kernel<64, 128, 128, 128, 64, 64>
        <<<dim3(1536, 1, 1), 256, DSMEM_CONV>>>(f1, wt2h, b2, f2);

    // conv3: 384 tiles x 2 N-chunks
    conv_mma_kernel<128, 256, 64, 64, 32, 32>
        <<<dim3(384, 2, 1), 256, DSMEM_CONV>>>(f2, wt3h, b3, f3);

    // sampling -> q fp16
    sample_kernel<<<1024, 256>>>(qp);

    // corr GEMM -> fp16 corr
    corr_mma_kernel<<<dim3(8, 4, 48), 256, DSMEM_CONV>>>();

    // softmax + expectation + occlusion (FFMA-pipe exp)
    finalize_kernel<<<3072, 256>>>((float*)d_out);
}